// round 4
// baseline (speedup 1.0000x reference)
#include <cuda_runtime.h>
#include <cuda_bf16.h>
#include <math.h>

#define N_NODES 50000
#define E_EDGES 800000
#define ET      (E_EDGES + N_NODES)   // 850000 edges incl. self loops
#define F_IN    128
#define H1      4
#define C1      64
#define HC1     256
#define C2      64
#define NEG_SLOPE 0.2f
#define EPS_DEN 1e-16f
#define NEG_KEY ((int)0x807FFFFF)     // ordered-int key of -inf

// ---------------- scratch (device globals; no allocation allowed) ------------
// 16-byte alignment required: accessed via float4 / red.global.add.v4.f32.
__device__ __align__(16) float g_h1[N_NODES * HC1];   // layer1 linear out  [N,4,64]
__device__ __align__(16) float g_o1[N_NODES * HC1];   // layer1 aggregated
__device__ __align__(16) float g_x2[N_NODES * HC1];   // elu(o1 + b1)
__device__ __align__(16) float g_h2[N_NODES * C2];    // layer2 linear out
__device__ __align__(16) float g_as1[N_NODES * H1];
__device__ __align__(16) float g_ad1[N_NODES * H1];
__device__ __align__(16) float g_as2[N_NODES];
__device__ __align__(16) float g_ad2[N_NODES];
__device__ __align__(16) int   g_m1[N_NODES * H1];    // ordered-int max keys
__device__ __align__(16) float g_s1[N_NODES * H1];
__device__ __align__(16) int   g_m2[N_NODES];
__device__ __align__(16) float g_s2[N_NODES];
__device__ __align__(16) float g_w1[ET * H1];
__device__ __align__(16) float g_w2[ET];
__device__ __align__(16) int   g_src[ET];
__device__ __align__(16) int   g_dst[ET];
__device__ int g_is64;   // 1 if edge_index buffer is int64, 0 if int32

// ---------------- helpers ----------------------------------------------------
__device__ __forceinline__ int fkey(float f) {
    int i = __float_as_int(f);
    return i >= 0 ? i : (i ^ 0x7FFFFFFF);
}
__device__ __forceinline__ float kinv(int k) {
    return __int_as_float(k >= 0 ? k : (k ^ 0x7FFFFFFF));
}
__device__ __forceinline__ void red_add_v4(float* p, float a, float b, float c, float d) {
    asm volatile("red.global.add.v4.f32 [%0], {%1,%2,%3,%4};"
                 :: "l"(p), "f"(a), "f"(b), "f"(c), "f"(d) : "memory");
}
__device__ __forceinline__ int clampN(int v) {
    return v < 0 ? 0 : (v >= N_NODES ? N_NODES - 1 : v);
}

// ---------------- edge-index dtype detection ---------------------------------
// Node ids < 50000. If the buffer is int64 (little-endian), every odd int32
// word is a zero high-half. If int32, odd words are random nonzero node ids.
__global__ void detect_kernel(const int* __restrict__ ei32) {
    int acc = 0;
    for (int i = 0; i < 128; i++) acc |= ei32[2 * i + 1];
    g_is64 = (acc == 0) ? 1 : 0;
}

// ---------------- edge list (append self loops) -------------------------------
__global__ void edges_kernel(const void* __restrict__ ei) {
    int i = blockIdx.x * blockDim.x + threadIdx.x;
    if (i >= ET) return;
    if (i < E_EDGES) {
        int s, d;
        if (g_is64) {
            const long long* p = (const long long*)ei;
            s = (int)p[i];
            d = (int)p[E_EDGES + i];
        } else {
            const int* p = (const int*)ei;
            s = p[i];
            d = p[E_EDGES + i];
        }
        g_src[i] = clampN(s);
        g_dst[i] = clampN(d);
    } else {
        int n = i - E_EDGES;
        g_src[i] = n;
        g_dst[i] = n;
    }
}

__global__ void init_seg_kernel() {
    int i = blockIdx.x * blockDim.x + threadIdx.x;
    if (i < N_NODES * H1) { g_m1[i] = NEG_KEY; g_s1[i] = 0.f; }
    if (i < N_NODES)      { g_m2[i] = NEG_KEY; g_s2[i] = 0.f; }
}

__global__ void zero_o1_kernel() {
    int i = blockIdx.x * blockDim.x + threadIdx.x;
    if (i < N_NODES * HC1) g_o1[i] = 0.f;
}

__global__ void out_init_kernel(float* __restrict__ out, const float* __restrict__ b2) {
    int i = blockIdx.x * blockDim.x + threadIdx.x;
    if (i < N_NODES * C2) out[i] = b2[i & (C2 - 1)];
}

// ---------------- SGEMM: C[M,NOUT] = A[M,K] @ B[K,NOUT], 64x64 tiles ---------
template<int K, int NOUT>
__global__ __launch_bounds__(256)
void sgemm_kernel(const float* __restrict__ A, const float* __restrict__ B,
                  float* __restrict__ C, int M) {
    __shared__ float As[16][64];
    __shared__ float Bs[16][64];
    int t = threadIdx.x;
    int tx = t & 15, ty = t >> 4;
    int rowBase = blockIdx.y * 64;
    int colBase = blockIdx.x * 64;
    int aRow = t >> 2, aC4 = t & 3;     // A loader: row 0..63, float4 chunk 0..3
    int bK = t >> 4, bC4 = t & 15;      // B loader: k 0..15, float4 chunk 0..15
    float acc[4][4] = {};
    for (int kt = 0; kt < K; kt += 16) {
        float4 av = make_float4(0.f, 0.f, 0.f, 0.f);
        int gr = rowBase + aRow;
        if (gr < M) av = *(const float4*)&A[(size_t)gr * K + kt + aC4 * 4];
        As[aC4 * 4 + 0][aRow] = av.x;
        As[aC4 * 4 + 1][aRow] = av.y;
        As[aC4 * 4 + 2][aRow] = av.z;
        As[aC4 * 4 + 3][aRow] = av.w;
        float4 bv = *(const float4*)&B[(size_t)(kt + bK) * NOUT + colBase + bC4 * 4];
        *(float4*)&Bs[bK][bC4 * 4] = bv;
        __syncthreads();
#pragma unroll
        for (int k = 0; k < 16; k++) {
            float4 a4 = *(const float4*)&As[k][ty * 4];
            float4 b4 = *(const float4*)&Bs[k][tx * 4];
            float a[4] = {a4.x, a4.y, a4.z, a4.w};
            float b[4] = {b4.x, b4.y, b4.z, b4.w};
#pragma unroll
            for (int i = 0; i < 4; i++)
#pragma unroll
                for (int j = 0; j < 4; j++)
                    acc[i][j] += a[i] * b[j];
        }
        __syncthreads();
    }
#pragma unroll
    for (int i = 0; i < 4; i++) {
        int gr = rowBase + ty * 4 + i;
        if (gr < M)
            *(float4*)&C[(size_t)gr * NOUT + colBase + tx * 4] =
                make_float4(acc[i][0], acc[i][1], acc[i][2], acc[i][3]);
    }
}

// ---------------- attention logits -------------------------------------------
__global__ void att1_kernel(const float* __restrict__ h,
                            const float* __restrict__ att_s,
                            const float* __restrict__ att_d) {
    int w = (blockIdx.x * blockDim.x + threadIdx.x) >> 5;
    int lane = threadIdx.x & 31;
    if (w >= N_NODES * H1) return;
    int n = w >> 2, hh = w & 3;
    const float* row = h + (size_t)n * HC1 + hh * C1;
    const float* sv = att_s + hh * C1;
    const float* dv = att_d + hh * C1;
    float s = row[lane] * sv[lane] + row[lane + 32] * sv[lane + 32];
    float d = row[lane] * dv[lane] + row[lane + 32] * dv[lane + 32];
#pragma unroll
    for (int o = 16; o; o >>= 1) {
        s += __shfl_down_sync(0xFFFFFFFFu, s, o);
        d += __shfl_down_sync(0xFFFFFFFFu, d, o);
    }
    if (lane == 0) { g_as1[w] = s; g_ad1[w] = d; }
}

__global__ void att2_kernel(const float* __restrict__ h,
                            const float* __restrict__ att_s,
                            const float* __restrict__ att_d) {
    int w = (blockIdx.x * blockDim.x + threadIdx.x) >> 5;
    int lane = threadIdx.x & 31;
    if (w >= N_NODES) return;
    const float* row = h + (size_t)w * C2;
    float s = row[lane] * att_s[lane] + row[lane + 32] * att_s[lane + 32];
    float d = row[lane] * att_d[lane] + row[lane + 32] * att_d[lane + 32];
#pragma unroll
    for (int o = 16; o; o >>= 1) {
        s += __shfl_down_sync(0xFFFFFFFFu, s, o);
        d += __shfl_down_sync(0xFFFFFFFFu, d, o);
    }
    if (lane == 0) { g_as2[w] = s; g_ad2[w] = d; }
}

// ---------------- edge passes layer 1 ----------------------------------------
__global__ void max1_kernel() {
    int i = blockIdx.x * blockDim.x + threadIdx.x;
    if (i >= ET * H1) return;
    int e = i >> 2, h = i & 3;
    int s = g_src[e], d = g_dst[e];
    float v = g_as1[s * 4 + h] + g_ad1[d * 4 + h];
    v = v > 0.f ? v : NEG_SLOPE * v;
    atomicMax(&g_m1[d * 4 + h], fkey(v));
}

__global__ void exp1_kernel() {
    int i = blockIdx.x * blockDim.x + threadIdx.x;
    if (i >= ET * H1) return;
    int e = i >> 2, h = i & 3;
    int s = g_src[e], d = g_dst[e];
    float v = g_as1[s * 4 + h] + g_ad1[d * 4 + h];
    v = v > 0.f ? v : NEG_SLOPE * v;
    float m = kinv(g_m1[d * 4 + h]);
    float w = expf(v - m);
    g_w1[i] = w;
    atomicAdd(&g_s1[d * 4 + h], w);
}

__global__ void agg1_kernel() {
    long long i = (long long)blockIdx.x * blockDim.x + threadIdx.x;
    if (i >= (long long)ET * 64) return;       // 54.4M threads
    int e = (int)(i >> 6), q = (int)(i & 63), h = q >> 4, c4 = q & 15;
    int s = g_src[e], d = g_dst[e];
    float alpha = g_w1[(e << 2) + h] / (g_s1[(d << 2) + h] + EPS_DEN);
    float4 v = *(const float4*)&g_h1[(size_t)s * HC1 + h * C1 + c4 * 4];
    float* p = &g_o1[(size_t)d * HC1 + h * C1 + c4 * 4];
    red_add_v4(p, alpha * v.x, alpha * v.y, alpha * v.z, alpha * v.w);
}

__global__ void elu_kernel(const float* __restrict__ b1) {
    int i = blockIdx.x * blockDim.x + threadIdx.x;
    if (i >= N_NODES * HC1) return;
    float v = g_o1[i] + b1[i & (HC1 - 1)];
    g_x2[i] = v > 0.f ? v : expm1f(v);
}

// ---------------- edge passes layer 2 ----------------------------------------
__global__ void max2_kernel() {
    int i = blockIdx.x * blockDim.x + threadIdx.x;
    if (i >= ET) return;
    int s = g_src[i], d = g_dst[i];
    float v = g_as2[s] + g_ad2[d];
    v = v > 0.f ? v : NEG_SLOPE * v;
    atomicMax(&g_m2[d], fkey(v));
}

__global__ void exp2_kernel() {
    int i = blockIdx.x * blockDim.x + threadIdx.x;
    if (i >= ET) return;
    int s = g_src[i], d = g_dst[i];
    float v = g_as2[s] + g_ad2[d];
    v = v > 0.f ? v : NEG_SLOPE * v;
    float m = kinv(g_m2[d]);
    float w = expf(v - m);
    g_w2[i] = w;
    atomicAdd(&g_s2[d], w);
}

__global__ void agg2_kernel(float* __restrict__ out) {
    long long i = (long long)blockIdx.x * blockDim.x + threadIdx.x;
    if (i >= (long long)ET * 16) return;       // 13.6M threads
    int e = (int)(i >> 4), c4 = (int)(i & 15);
    int s = g_src[e], d = g_dst[e];
    float alpha = g_w2[e] / (g_s2[d] + EPS_DEN);
    float4 v = *(const float4*)&g_h2[(size_t)s * C2 + c4 * 4];
    float* p = &out[(size_t)d * C2 + c4 * 4];
    red_add_v4(p, alpha * v.x, alpha * v.y, alpha * v.z, alpha * v.w);
}

// ---------------- launch ------------------------------------------------------
static inline int cdiv(long long a, int b) { return (int)((a + b - 1) / b); }

extern "C" void kernel_launch(void* const* d_in, const int* in_sizes, int n_in,
                              void* d_out, int out_size) {
    const float* x        = (const float*)d_in[0];
    const void*  ei       = d_in[1];            // int32 or int64, detected on device
    const float* W1       = (const float*)d_in[2];
    const float* att_src1 = (const float*)d_in[3];
    const float* att_dst1 = (const float*)d_in[4];
    const float* b1       = (const float*)d_in[5];
    const float* W2       = (const float*)d_in[6];
    const float* att_src2 = (const float*)d_in[7];
    const float* att_dst2 = (const float*)d_in[8];
    const float* b2       = (const float*)d_in[9];
    float* out = (float*)d_out;

    float* h1 = nullptr; float* x2 = nullptr; float* h2 = nullptr;
    cudaGetSymbolAddress((void**)&h1, g_h1);
    cudaGetSymbolAddress((void**)&x2, g_x2);
    cudaGetSymbolAddress((void**)&h2, g_h2);

    const int T = 256;

    detect_kernel<<<1, 1>>>((const int*)ei);
    edges_kernel<<<cdiv(ET, T), T>>>(ei);
    init_seg_kernel<<<cdiv(N_NODES * H1, T), T>>>();
    zero_o1_kernel<<<cdiv((long long)N_NODES * HC1, T), T>>>();

    // ---- layer 1 ----
    {
        dim3 grid(HC1 / 64, cdiv(N_NODES, 64));
        sgemm_kernel<F_IN, HC1><<<grid, T>>>(x, W1, h1, N_NODES);
    }
    att1_kernel<<<cdiv((long long)N_NODES * H1 * 32, T), T>>>(h1, att_src1, att_dst1);
    max1_kernel<<<cdiv((long long)ET * H1, T), T>>>();
    exp1_kernel<<<cdiv((long long)ET * H1, T), T>>>();
    agg1_kernel<<<cdiv((long long)ET * 64, T), T>>>();
    elu_kernel<<<cdiv((long long)N_NODES * HC1, T), T>>>(b1);

    // ---- layer 2 ----
    {
        dim3 grid(C2 / 64, cdiv(N_NODES, 64));
        sgemm_kernel<HC1, C2><<<grid, T>>>(x2, W2, h2, N_NODES);
    }
    att2_kernel<<<cdiv((long long)N_NODES * 32, T), T>>>(h2, att_src2, att_dst2);
    out_init_kernel<<<cdiv((long long)N_NODES * C2, T), T>>>(out, b2);
    max2_kernel<<<cdiv(ET, T), T>>>();
    exp2_kernel<<<cdiv(ET, T), T>>>();
    agg2_kernel<<<cdiv((long long)ET * 16, T), T>>>(out);
}

// round 5
// speedup vs baseline: 1.3090x; 1.3090x over previous
#include <cuda_runtime.h>
#include <cuda_bf16.h>
#include <math.h>

#define N_NODES 50000
#define E_EDGES 800000
#define ET      (E_EDGES + N_NODES)   // 850000 edges incl. self loops
#define F_IN    128
#define H1      4
#define C1      64
#define HC1     256
#define C2      64
#define NEG_SLOPE 0.2f
#define EPS_DEN 1e-16f

// ---------------- scratch (device globals; 16B-aligned for float4) -----------
__device__ __align__(16) float g_h1[N_NODES * HC1];   // layer1 linear out
__device__ __align__(16) float g_x2[N_NODES * HC1];   // elu(agg1 + b1)
__device__ __align__(16) float g_h2[N_NODES * C2];    // layer2 linear out
__device__ __align__(16) float g_as1[N_NODES * H1];
__device__ __align__(16) float g_ad1[N_NODES * H1];
__device__ __align__(16) float g_as2[N_NODES];
__device__ __align__(16) float g_ad2[N_NODES];
__device__ __align__(16) float g_alpha1[ET * H1];     // per-edge alpha (CSR order)
__device__ __align__(16) float g_alpha2[ET];
__device__ __align__(16) int   g_src[ET];
__device__ __align__(16) int   g_dst[ET];
__device__ __align__(16) int   g_csr_src[ET];         // src sorted by dst
__device__ __align__(16) int   g_rowptr[N_NODES + 1];
__device__ __align__(16) int   g_cursor[N_NODES];
__device__ int g_is64;

// ---------------- helpers ----------------------------------------------------
__device__ __forceinline__ int clampN(int v) {
    return v < 0 ? 0 : (v >= N_NODES ? N_NODES - 1 : v);
}
__device__ __forceinline__ float lrelu(float v) {
    return v > 0.f ? v : NEG_SLOPE * v;
}

// ---------------- edge-index dtype detection ---------------------------------
__global__ void detect_kernel(const int* __restrict__ ei32) {
    int acc = 0;
    for (int i = 0; i < 128; i++) acc |= ei32[2 * i + 1];
    g_is64 = (acc == 0) ? 1 : 0;
}

__global__ void zero_cursor_kernel() {
    int i = blockIdx.x * blockDim.x + threadIdx.x;
    if (i < N_NODES) g_cursor[i] = 0;
}

// decode edges (+self loops) and histogram in-degree into g_cursor
__global__ void edges_kernel(const void* __restrict__ ei) {
    int i = blockIdx.x * blockDim.x + threadIdx.x;
    if (i >= ET) return;
    int s, d;
    if (i < E_EDGES) {
        if (g_is64) {
            const long long* p = (const long long*)ei;
            s = (int)p[i];  d = (int)p[E_EDGES + i];
        } else {
            const int* p = (const int*)ei;
            s = p[i];  d = p[E_EDGES + i];
        }
        s = clampN(s); d = clampN(d);
    } else {
        s = d = i - E_EDGES;
    }
    g_src[i] = s;
    g_dst[i] = d;
    atomicAdd(&g_cursor[d], 1);
}

// single-block exclusive scan of degrees -> rowptr, cursor
__global__ __launch_bounds__(1024) void scan_kernel() {
    __shared__ int part[1024];
    int t = threadIdx.x;
    const int CH = (N_NODES + 1023) / 1024;   // 49
    int base = t * CH;
    int sum = 0;
    for (int i = 0; i < CH; i++) {
        int n = base + i;
        if (n < N_NODES) sum += g_cursor[n];
    }
    part[t] = sum;
    __syncthreads();
    for (int off = 1; off < 1024; off <<= 1) {
        int v = (t >= off) ? part[t - off] : 0;
        __syncthreads();
        part[t] += v;
        __syncthreads();
    }
    int run = part[t] - sum;                  // exclusive base
    for (int i = 0; i < CH; i++) {
        int n = base + i;
        if (n < N_NODES) {
            int dg = g_cursor[n];
            g_rowptr[n] = run;
            g_cursor[n] = run;
            run += dg;
        }
    }
    if (t == 1023) g_rowptr[N_NODES] = part[1023];
}

__global__ void scatter_kernel() {
    int i = blockIdx.x * blockDim.x + threadIdx.x;
    if (i >= ET) return;
    int pos = atomicAdd(&g_cursor[g_dst[i]], 1);
    g_csr_src[pos] = g_src[i];
}

// ---------------- SGEMM: C[M,NOUT] = A[M,K] @ B[K,NOUT], 64x64 tiles ---------
template<int K, int NOUT>
__global__ __launch_bounds__(256)
void sgemm_kernel(const float* __restrict__ A, const float* __restrict__ B,
                  float* __restrict__ C, int M) {
    __shared__ float As[16][64];
    __shared__ float Bs[16][64];
    int t = threadIdx.x;
    int tx = t & 15, ty = t >> 4;
    int rowBase = blockIdx.y * 64;
    int colBase = blockIdx.x * 64;
    int aRow = t >> 2, aC4 = t & 3;
    int bK = t >> 4, bC4 = t & 15;
    float acc[4][4] = {};
    for (int kt = 0; kt < K; kt += 16) {
        float4 av = make_float4(0.f, 0.f, 0.f, 0.f);
        int gr = rowBase + aRow;
        if (gr < M) av = *(const float4*)&A[(size_t)gr * K + kt + aC4 * 4];
        As[aC4 * 4 + 0][aRow] = av.x;
        As[aC4 * 4 + 1][aRow] = av.y;
        As[aC4 * 4 + 2][aRow] = av.z;
        As[aC4 * 4 + 3][aRow] = av.w;
        float4 bv = *(const float4*)&B[(size_t)(kt + bK) * NOUT + colBase + bC4 * 4];
        *(float4*)&Bs[bK][bC4 * 4] = bv;
        __syncthreads();
#pragma unroll
        for (int k = 0; k < 16; k++) {
            float4 a4 = *(const float4*)&As[k][ty * 4];
            float4 b4 = *(const float4*)&Bs[k][tx * 4];
            float a[4] = {a4.x, a4.y, a4.z, a4.w};
            float b[4] = {b4.x, b4.y, b4.z, b4.w};
#pragma unroll
            for (int i = 0; i < 4; i++)
#pragma unroll
                for (int j = 0; j < 4; j++)
                    acc[i][j] += a[i] * b[j];
        }
        __syncthreads();
    }
#pragma unroll
    for (int i = 0; i < 4; i++) {
        int gr = rowBase + ty * 4 + i;
        if (gr < M)
            *(float4*)&C[(size_t)gr * NOUT + colBase + tx * 4] =
                make_float4(acc[i][0], acc[i][1], acc[i][2], acc[i][3]);
    }
}

// ---------------- attention logits -------------------------------------------
__global__ void att1_kernel(const float* __restrict__ h,
                            const float* __restrict__ att_s,
                            const float* __restrict__ att_d) {
    int w = (blockIdx.x * blockDim.x + threadIdx.x) >> 5;
    int lane = threadIdx.x & 31;
    if (w >= N_NODES * H1) return;
    int n = w >> 2, hh = w & 3;
    const float* row = h + (size_t)n * HC1 + hh * C1;
    const float* sv = att_s + hh * C1;
    const float* dv = att_d + hh * C1;
    float s = row[lane] * sv[lane] + row[lane + 32] * sv[lane + 32];
    float d = row[lane] * dv[lane] + row[lane + 32] * dv[lane + 32];
#pragma unroll
    for (int o = 16; o; o >>= 1) {
        s += __shfl_down_sync(0xFFFFFFFFu, s, o);
        d += __shfl_down_sync(0xFFFFFFFFu, d, o);
    }
    if (lane == 0) { g_as1[w] = s; g_ad1[w] = d; }
}

__global__ void att2_kernel(const float* __restrict__ h,
                            const float* __restrict__ att_s,
                            const float* __restrict__ att_d) {
    int w = (blockIdx.x * blockDim.x + threadIdx.x) >> 5;
    int lane = threadIdx.x & 31;
    if (w >= N_NODES) return;
    const float* row = h + (size_t)w * C2;
    float s = row[lane] * att_s[lane] + row[lane + 32] * att_s[lane + 32];
    float d = row[lane] * att_d[lane] + row[lane + 32] * att_d[lane + 32];
#pragma unroll
    for (int o = 16; o; o >>= 1) {
        s += __shfl_down_sync(0xFFFFFFFFu, s, o);
        d += __shfl_down_sync(0xFFFFFFFFu, d, o);
    }
    if (lane == 0) { g_as2[w] = s; g_ad2[w] = d; }
}

// ---------------- per-node softmax (warp per node), writes alpha -------------
__global__ void softmax1_kernel() {
    int w = (blockIdx.x * blockDim.x + threadIdx.x) >> 5;
    int lane = threadIdx.x & 31;
    if (w >= N_NODES) return;
    int lo = g_rowptr[w], hi = g_rowptr[w + 1];
    float4 ad = *(const float4*)&g_ad1[w * 4];
    float m0 = -1e30f, m1 = -1e30f, m2 = -1e30f, m3 = -1e30f;
    float s0 = 0.f, s1 = 0.f, s2 = 0.f, s3 = 0.f;
    for (int k = lo + lane; k < hi; k += 32) {
        int s = g_csr_src[k];
        float4 as = *(const float4*)&g_as1[s * 4];
        float v0 = lrelu(as.x + ad.x), v1 = lrelu(as.y + ad.y);
        float v2 = lrelu(as.z + ad.z), v3 = lrelu(as.w + ad.w);
        if (v0 > m0) { s0 *= __expf(m0 - v0); m0 = v0; }  s0 += __expf(v0 - m0);
        if (v1 > m1) { s1 *= __expf(m1 - v1); m1 = v1; }  s1 += __expf(v1 - m1);
        if (v2 > m2) { s2 *= __expf(m2 - v2); m2 = v2; }  s2 += __expf(v2 - m2);
        if (v3 > m3) { s3 *= __expf(m3 - v3); m3 = v3; }  s3 += __expf(v3 - m3);
    }
#pragma unroll
    for (int off = 16; off; off >>= 1) {
        float mo, so, mn;
        mo = __shfl_xor_sync(0xFFFFFFFFu, m0, off); so = __shfl_xor_sync(0xFFFFFFFFu, s0, off);
        mn = fmaxf(m0, mo); s0 = s0 * __expf(m0 - mn) + so * __expf(mo - mn); m0 = mn;
        mo = __shfl_xor_sync(0xFFFFFFFFu, m1, off); so = __shfl_xor_sync(0xFFFFFFFFu, s1, off);
        mn = fmaxf(m1, mo); s1 = s1 * __expf(m1 - mn) + so * __expf(mo - mn); m1 = mn;
        mo = __shfl_xor_sync(0xFFFFFFFFu, m2, off); so = __shfl_xor_sync(0xFFFFFFFFu, s2, off);
        mn = fmaxf(m2, mo); s2 = s2 * __expf(m2 - mn) + so * __expf(mo - mn); m2 = mn;
        mo = __shfl_xor_sync(0xFFFFFFFFu, m3, off); so = __shfl_xor_sync(0xFFFFFFFFu, s3, off);
        mn = fmaxf(m3, mo); s3 = s3 * __expf(m3 - mn) + so * __expf(mo - mn); m3 = mn;
    }
    float i0 = 1.f / (s0 + EPS_DEN), i1 = 1.f / (s1 + EPS_DEN);
    float i2 = 1.f / (s2 + EPS_DEN), i3 = 1.f / (s3 + EPS_DEN);
    for (int k = lo + lane; k < hi; k += 32) {
        int s = g_csr_src[k];
        float4 as = *(const float4*)&g_as1[s * 4];
        float a0 = __expf(lrelu(as.x + ad.x) - m0) * i0;
        float a1 = __expf(lrelu(as.y + ad.y) - m1) * i1;
        float a2 = __expf(lrelu(as.z + ad.z) - m2) * i2;
        float a3 = __expf(lrelu(as.w + ad.w) - m3) * i3;
        *(float4*)&g_alpha1[k * 4] = make_float4(a0, a1, a2, a3);
    }
}

__global__ void softmax2_kernel() {
    int w = (blockIdx.x * blockDim.x + threadIdx.x) >> 5;
    int lane = threadIdx.x & 31;
    if (w >= N_NODES) return;
    int lo = g_rowptr[w], hi = g_rowptr[w + 1];
    float ad = g_ad2[w];
    float m = -1e30f, s = 0.f;
    for (int k = lo + lane; k < hi; k += 32) {
        float v = lrelu(g_as2[g_csr_src[k]] + ad);
        if (v > m) { s *= __expf(m - v); m = v; }
        s += __expf(v - m);
    }
#pragma unroll
    for (int off = 16; off; off >>= 1) {
        float mo = __shfl_xor_sync(0xFFFFFFFFu, m, off);
        float so = __shfl_xor_sync(0xFFFFFFFFu, s, off);
        float mn = fmaxf(m, mo);
        s = s * __expf(m - mn) + so * __expf(mo - mn);
        m = mn;
    }
    float inv = 1.f / (s + EPS_DEN);
    for (int k = lo + lane; k < hi; k += 32) {
        float v = lrelu(g_as2[g_csr_src[k]] + ad);
        g_alpha2[k] = __expf(v - m) * inv;
    }
}

// ---------------- aggregation (block per node, coalesced row gather) ---------
__global__ __launch_bounds__(256)
void agg1_kernel(const float* __restrict__ b1) {
    int n = blockIdx.x;
    int ch = threadIdx.x;
    int h = ch >> 6;
    int lo = g_rowptr[n], hi = g_rowptr[n + 1];
    float acc = 0.f;
    for (int k = lo; k < hi; k++) {
        int s = g_csr_src[k];
        float a = g_alpha1[k * 4 + h];
        acc += a * g_h1[(size_t)s * HC1 + ch];
    }
    float v = acc + b1[ch];
    g_x2[(size_t)n * HC1 + ch] = v > 0.f ? v : expm1f(v);
}

__global__ __launch_bounds__(64)
void agg2_kernel(float* __restrict__ out, const float* __restrict__ b2) {
    int n = blockIdx.x;
    int ch = threadIdx.x;
    int lo = g_rowptr[n], hi = g_rowptr[n + 1];
    float acc = 0.f;
    for (int k = lo; k < hi; k++) {
        int s = g_csr_src[k];
        acc += g_alpha2[k] * g_h2[(size_t)s * C2 + ch];
    }
    out[(size_t)n * C2 + ch] = acc + b2[ch];
}

// ---------------- launch ------------------------------------------------------
static inline int cdiv(long long a, int b) { return (int)((a + b - 1) / b); }

extern "C" void kernel_launch(void* const* d_in, const int* in_sizes, int n_in,
                              void* d_out, int out_size) {
    const float* x        = (const float*)d_in[0];
    const void*  ei       = d_in[1];
    const float* W1       = (const float*)d_in[2];
    const float* att_src1 = (const float*)d_in[3];
    const float* att_dst1 = (const float*)d_in[4];
    const float* b1       = (const float*)d_in[5];
    const float* W2       = (const float*)d_in[6];
    const float* att_src2 = (const float*)d_in[7];
    const float* att_dst2 = (const float*)d_in[8];
    const float* b2       = (const float*)d_in[9];
    float* out = (float*)d_out;

    float* h1 = nullptr; float* x2 = nullptr; float* h2 = nullptr;
    cudaGetSymbolAddress((void**)&h1, g_h1);
    cudaGetSymbolAddress((void**)&x2, g_x2);
    cudaGetSymbolAddress((void**)&h2, g_h2);

    const int T = 256;

    // ---- CSR build ----
    detect_kernel<<<1, 1>>>((const int*)ei);
    zero_cursor_kernel<<<cdiv(N_NODES, T), T>>>();
    edges_kernel<<<cdiv(ET, T), T>>>(ei);
    scan_kernel<<<1, 1024>>>();
    scatter_kernel<<<cdiv(ET, T), T>>>();

    // ---- layer 1 ----
    {
        dim3 grid(HC1 / 64, cdiv(N_NODES, 64));
        sgemm_kernel<F_IN, HC1><<<grid, T>>>(x, W1, h1, N_NODES);
    }
    att1_kernel<<<cdiv((long long)N_NODES * H1 * 32, T), T>>>(h1, att_src1, att_dst1);
    softmax1_kernel<<<cdiv((long long)N_NODES * 32, T), T>>>();
    agg1_kernel<<<N_NODES, 256>>>(b1);

    // ---- layer 2 ----
    {
        dim3 grid(C2 / 64, cdiv(N_NODES, 64));
        sgemm_kernel<HC1, C2><<<grid, T>>>(x2, W2, h2, N_NODES);
    }
    att2_kernel<<<cdiv((long long)N_NODES * 32, T), T>>>(h2, att_src2, att_dst2);
    softmax2_kernel<<<cdiv((long long)N_NODES * 32, T), T>>>();
    agg2_kernel<<<N_NODES, 64>>>(out, b2);
}

// round 6
// speedup vs baseline: 1.5261x; 1.1659x over previous
#include <cuda_runtime.h>
#include <cuda_bf16.h>
#include <math.h>

#define N_NODES 50000
#define E_EDGES 800000
#define ET      (E_EDGES + N_NODES)   // 850000 edges incl. self loops
#define F_IN    128
#define H1      4
#define C1      64
#define HC1     256
#define C2      64
#define NEG_SLOPE 0.2f
#define EPS_DEN 1e-16f
#define SCAN_B  1024
#define NBLK    ((N_NODES + SCAN_B - 1) / SCAN_B)   // 49

// ---------------- scratch (device globals; 16B-aligned for float4) -----------
__device__ __align__(16) float g_h1[N_NODES * HC1];   // layer1 linear out
__device__ __align__(16) float g_x2[N_NODES * HC1];   // elu(agg1 + b1)
__device__ __align__(16) float g_h2[N_NODES * C2];    // layer2 linear out
__device__ __align__(16) float g_as1[N_NODES * H1];
__device__ __align__(16) float g_ad1[N_NODES * H1];
__device__ __align__(16) float g_as2[N_NODES];
__device__ __align__(16) float g_ad2[N_NODES];
__device__ __align__(16) float g_alpha1[ET * H1];     // per-edge alpha (CSR order)
__device__ __align__(16) float g_alpha2[ET];
__device__ __align__(16) int   g_src[ET];
__device__ __align__(16) int   g_dst[ET];
__device__ __align__(16) int   g_csr_src[ET];         // src sorted by dst
__device__ __align__(16) int   g_rowptr[N_NODES + 1];
__device__ __align__(16) int   g_cursor[N_NODES];
__device__ __align__(16) int   g_deg[N_NODES];
__device__ __align__(16) int   g_bsum[NBLK];
__device__ __align__(16) int   g_boff[NBLK];
__device__ int g_is64;

// ---------------- helpers ----------------------------------------------------
__device__ __forceinline__ int clampN(int v) {
    return v < 0 ? 0 : (v >= N_NODES ? N_NODES - 1 : v);
}
__device__ __forceinline__ float lrelu(float v) {
    return v > 0.f ? v : NEG_SLOPE * v;
}

// ---------------- edge-index dtype detection (1 warp) -------------------------
__global__ void detect_kernel(const int* __restrict__ ei32) {
    int lane = threadIdx.x;
    int v = ei32[2 * lane + 1] | ei32[2 * (lane + 32) + 1] |
            ei32[2 * (lane + 64) + 1] | ei32[2 * (lane + 96) + 1];
#pragma unroll
    for (int o = 16; o; o >>= 1) v |= __shfl_xor_sync(0xFFFFFFFFu, v, o);
    if (lane == 0) g_is64 = (v == 0) ? 1 : 0;
}

__global__ void zero_deg_kernel() {
    int i = blockIdx.x * blockDim.x + threadIdx.x;
    if (i < N_NODES) g_deg[i] = 0;
}

// decode edges (+self loops) and histogram in-degree into g_deg
__global__ void edges_kernel(const void* __restrict__ ei) {
    int i = blockIdx.x * blockDim.x + threadIdx.x;
    if (i >= ET) return;
    int s, d;
    if (i < E_EDGES) {
        if (g_is64) {
            const long long* p = (const long long*)ei;
            s = (int)p[i];  d = (int)p[E_EDGES + i];
        } else {
            const int* p = (const int*)ei;
            s = p[i];  d = p[E_EDGES + i];
        }
        s = clampN(s); d = clampN(d);
    } else {
        s = d = i - E_EDGES;
    }
    g_src[i] = s;
    g_dst[i] = d;
    atomicAdd(&g_deg[d], 1);
}

// ---------------- 3-phase parallel scan of g_deg -> g_rowptr ------------------
__global__ __launch_bounds__(SCAN_B) void scan_partial_kernel() {
    __shared__ int red[32];
    int i = blockIdx.x * SCAN_B + threadIdx.x;
    int v = (i < N_NODES) ? g_deg[i] : 0;
#pragma unroll
    for (int o = 16; o; o >>= 1) v += __shfl_down_sync(0xFFFFFFFFu, v, o);
    if ((threadIdx.x & 31) == 0) red[threadIdx.x >> 5] = v;
    __syncthreads();
    if (threadIdx.x < 32) {
        int r = red[threadIdx.x];
#pragma unroll
        for (int o = 16; o; o >>= 1) r += __shfl_down_sync(0xFFFFFFFFu, r, o);
        if (threadIdx.x == 0) g_bsum[blockIdx.x] = r;
    }
}

__global__ void scan_tops_kernel() {        // 1 warp, NBLK=49 values
    int lane = threadIdx.x;
    int v0 = (lane < NBLK) ? g_bsum[lane] : 0;
    int v1 = (lane + 32 < NBLK) ? g_bsum[lane + 32] : 0;
    // inclusive scan of the 64-value sequence [v0(0..31), v1(0..31)]
    int a = v0;
#pragma unroll
    for (int o = 1; o < 32; o <<= 1) {
        int t = __shfl_up_sync(0xFFFFFFFFu, a, o);
        if (lane >= o) a += t;
    }
    int tot0 = __shfl_sync(0xFFFFFFFFu, a, 31);
    int b = v1;
#pragma unroll
    for (int o = 1; o < 32; o <<= 1) {
        int t = __shfl_up_sync(0xFFFFFFFFu, b, o);
        if (lane >= o) b += t;
    }
    b += tot0;
    if (lane < NBLK) g_boff[lane] = a - v0;                 // exclusive
    if (lane + 32 < NBLK) g_boff[lane + 32] = b - v1;
    if (lane == 31) g_rowptr[N_NODES] = (NBLK > 32) ? __shfl_sync(0xFFFFFFFFu, b, 31)
                                                    : tot0;
}

__global__ __launch_bounds__(SCAN_B) void scan_final_kernel() {
    __shared__ int sh[SCAN_B];
    __shared__ int warp_tot[32];
    int i = blockIdx.x * SCAN_B + threadIdx.x;
    int v = (i < N_NODES) ? g_deg[i] : 0;
    int lane = threadIdx.x & 31, w = threadIdx.x >> 5;
    int a = v;
#pragma unroll
    for (int o = 1; o < 32; o <<= 1) {
        int t = __shfl_up_sync(0xFFFFFFFFu, a, o);
        if (lane >= o) a += t;
    }
    if (lane == 31) warp_tot[w] = a;
    __syncthreads();
    if (threadIdx.x < 32) {
        int t = warp_tot[threadIdx.x];
        int s = t;
#pragma unroll
        for (int o = 1; o < 32; o <<= 1) {
            int u = __shfl_up_sync(0xFFFFFFFFu, s, o);
            if (threadIdx.x >= o) s += u;
        }
        warp_tot[threadIdx.x] = s - t;                       // exclusive warp base
    }
    __syncthreads();
    int excl = a - v + warp_tot[w] + g_boff[blockIdx.x];
    if (i < N_NODES) { g_rowptr[i] = excl; g_cursor[i] = excl; }
    (void)sh;
}

__global__ void scatter_kernel() {
    int i = blockIdx.x * blockDim.x + threadIdx.x;
    if (i >= ET) return;
    int pos = atomicAdd(&g_cursor[g_dst[i]], 1);
    g_csr_src[pos] = g_src[i];
}

// ---------------- SGEMM: C[M,NOUT] = A[M,K] @ B[K,NOUT], 64x64 tiles ---------
template<int K, int NOUT>
__global__ __launch_bounds__(256)
void sgemm_kernel(const float* __restrict__ A, const float* __restrict__ B,
                  float* __restrict__ C, int M) {
    __shared__ float As[16][64];
    __shared__ float Bs[16][64];
    int t = threadIdx.x;
    int tx = t & 15, ty = t >> 4;
    int rowBase = blockIdx.y * 64;
    int colBase = blockIdx.x * 64;
    int aRow = t >> 2, aC4 = t & 3;
    int bK = t >> 4, bC4 = t & 15;
    float acc[4][4] = {};
    for (int kt = 0; kt < K; kt += 16) {
        float4 av = make_float4(0.f, 0.f, 0.f, 0.f);
        int gr = rowBase + aRow;
        if (gr < M) av = *(const float4*)&A[(size_t)gr * K + kt + aC4 * 4];
        As[aC4 * 4 + 0][aRow] = av.x;
        As[aC4 * 4 + 1][aRow] = av.y;
        As[aC4 * 4 + 2][aRow] = av.z;
        As[aC4 * 4 + 3][aRow] = av.w;
        float4 bv = *(const float4*)&B[(size_t)(kt + bK) * NOUT + colBase + bC4 * 4];
        *(float4*)&Bs[bK][bC4 * 4] = bv;
        __syncthreads();
#pragma unroll
        for (int k = 0; k < 16; k++) {
            float4 a4 = *(const float4*)&As[k][ty * 4];
            float4 b4 = *(const float4*)&Bs[k][tx * 4];
            float a[4] = {a4.x, a4.y, a4.z, a4.w};
            float b[4] = {b4.x, b4.y, b4.z, b4.w};
#pragma unroll
            for (int i = 0; i < 4; i++)
#pragma unroll
                for (int j = 0; j < 4; j++)
                    acc[i][j] += a[i] * b[j];
        }
        __syncthreads();
    }
#pragma unroll
    for (int i = 0; i < 4; i++) {
        int gr = rowBase + ty * 4 + i;
        if (gr < M)
            *(float4*)&C[(size_t)gr * NOUT + colBase + tx * 4] =
                make_float4(acc[i][0], acc[i][1], acc[i][2], acc[i][3]);
    }
}

// ---------------- attention logits -------------------------------------------
__global__ void att1_kernel(const float* __restrict__ h,
                            const float* __restrict__ att_s,
                            const float* __restrict__ att_d) {
    int w = (blockIdx.x * blockDim.x + threadIdx.x) >> 5;
    int lane = threadIdx.x & 31;
    if (w >= N_NODES * H1) return;
    int n = w >> 2, hh = w & 3;
    const float* row = h + (size_t)n * HC1 + hh * C1;
    const float* sv = att_s + hh * C1;
    const float* dv = att_d + hh * C1;
    float s = row[lane] * sv[lane] + row[lane + 32] * sv[lane + 32];
    float d = row[lane] * dv[lane] + row[lane + 32] * dv[lane + 32];
#pragma unroll
    for (int o = 16; o; o >>= 1) {
        s += __shfl_down_sync(0xFFFFFFFFu, s, o);
        d += __shfl_down_sync(0xFFFFFFFFu, d, o);
    }
    if (lane == 0) { g_as1[w] = s; g_ad1[w] = d; }
}

__global__ void att2_kernel(const float* __restrict__ h,
                            const float* __restrict__ att_s,
                            const float* __restrict__ att_d) {
    int w = (blockIdx.x * blockDim.x + threadIdx.x) >> 5;
    int lane = threadIdx.x & 31;
    if (w >= N_NODES) return;
    const float* row = h + (size_t)w * C2;
    float s = row[lane] * att_s[lane] + row[lane + 32] * att_s[lane + 32];
    float d = row[lane] * att_d[lane] + row[lane + 32] * att_d[lane + 32];
#pragma unroll
    for (int o = 16; o; o >>= 1) {
        s += __shfl_down_sync(0xFFFFFFFFu, s, o);
        d += __shfl_down_sync(0xFFFFFFFFu, d, o);
    }
    if (lane == 0) { g_as2[w] = s; g_ad2[w] = d; }
}

// ---------------- per-node softmax (warp per node), writes alpha -------------
__global__ void softmax1_kernel() {
    int w = (blockIdx.x * blockDim.x + threadIdx.x) >> 5;
    int lane = threadIdx.x & 31;
    if (w >= N_NODES) return;
    int lo = g_rowptr[w], hi = g_rowptr[w + 1];
    float4 ad = *(const float4*)&g_ad1[w * 4];
    float m0 = -1e30f, m1 = -1e30f, m2 = -1e30f, m3 = -1e30f;
    float s0 = 0.f, s1 = 0.f, s2 = 0.f, s3 = 0.f;
    for (int k = lo + lane; k < hi; k += 32) {
        int s = g_csr_src[k];
        float4 as = *(const float4*)&g_as1[s * 4];
        float v0 = lrelu(as.x + ad.x), v1 = lrelu(as.y + ad.y);
        float v2 = lrelu(as.z + ad.z), v3 = lrelu(as.w + ad.w);
        if (v0 > m0) { s0 *= __expf(m0 - v0); m0 = v0; }  s0 += __expf(v0 - m0);
        if (v1 > m1) { s1 *= __expf(m1 - v1); m1 = v1; }  s1 += __expf(v1 - m1);
        if (v2 > m2) { s2 *= __expf(m2 - v2); m2 = v2; }  s2 += __expf(v2 - m2);
        if (v3 > m3) { s3 *= __expf(m3 - v3); m3 = v3; }  s3 += __expf(v3 - m3);
    }
#pragma unroll
    for (int off = 16; off; off >>= 1) {
        float mo, so, mn;
        mo = __shfl_xor_sync(0xFFFFFFFFu, m0, off); so = __shfl_xor_sync(0xFFFFFFFFu, s0, off);
        mn = fmaxf(m0, mo); s0 = s0 * __expf(m0 - mn) + so * __expf(mo - mn); m0 = mn;
        mo = __shfl_xor_sync(0xFFFFFFFFu, m1, off); so = __shfl_xor_sync(0xFFFFFFFFu, s1, off);
        mn = fmaxf(m1, mo); s1 = s1 * __expf(m1 - mn) + so * __expf(mo - mn); m1 = mn;
        mo = __shfl_xor_sync(0xFFFFFFFFu, m2, off); so = __shfl_xor_sync(0xFFFFFFFFu, s2, off);
        mn = fmaxf(m2, mo); s2 = s2 * __expf(m2 - mn) + so * __expf(mo - mn); m2 = mn;
        mo = __shfl_xor_sync(0xFFFFFFFFu, m3, off); so = __shfl_xor_sync(0xFFFFFFFFu, s3, off);
        mn = fmaxf(m3, mo); s3 = s3 * __expf(m3 - mn) + so * __expf(mo - mn); m3 = mn;
    }
    float i0 = 1.f / (s0 + EPS_DEN), i1 = 1.f / (s1 + EPS_DEN);
    float i2 = 1.f / (s2 + EPS_DEN), i3 = 1.f / (s3 + EPS_DEN);
    for (int k = lo + lane; k < hi; k += 32) {
        int s = g_csr_src[k];
        float4 as = *(const float4*)&g_as1[s * 4];
        float a0 = __expf(lrelu(as.x + ad.x) - m0) * i0;
        float a1 = __expf(lrelu(as.y + ad.y) - m1) * i1;
        float a2 = __expf(lrelu(as.z + ad.z) - m2) * i2;
        float a3 = __expf(lrelu(as.w + ad.w) - m3) * i3;
        *(float4*)&g_alpha1[k * 4] = make_float4(a0, a1, a2, a3);
    }
}

__global__ void softmax2_kernel() {
    int w = (blockIdx.x * blockDim.x + threadIdx.x) >> 5;
    int lane = threadIdx.x & 31;
    if (w >= N_NODES) return;
    int lo = g_rowptr[w], hi = g_rowptr[w + 1];
    float ad = g_ad2[w];
    float m = -1e30f, s = 0.f;
    for (int k = lo + lane; k < hi; k += 32) {
        float v = lrelu(g_as2[g_csr_src[k]] + ad);
        if (v > m) { s *= __expf(m - v); m = v; }
        s += __expf(v - m);
    }
#pragma unroll
    for (int off = 16; off; off >>= 1) {
        float mo = __shfl_xor_sync(0xFFFFFFFFu, m, off);
        float so = __shfl_xor_sync(0xFFFFFFFFu, s, off);
        float mn = fmaxf(m, mo);
        s = s * __expf(m - mn) + so * __expf(mo - mn);
        m = mn;
    }
    float inv = 1.f / (s + EPS_DEN);
    for (int k = lo + lane; k < hi; k += 32) {
        float v = lrelu(g_as2[g_csr_src[k]] + ad);
        g_alpha2[k] = __expf(v - m) * inv;
    }
}

// ---------------- aggregation (block per node, coalesced row gather) ---------
__global__ __launch_bounds__(256)
void agg1_kernel(const float* __restrict__ b1) {
    int n = blockIdx.x;
    int ch = threadIdx.x;
    int h = ch >> 6;
    int lo = g_rowptr[n], hi = g_rowptr[n + 1];
    float acc = 0.f;
    for (int k = lo; k < hi; k++) {
        int s = g_csr_src[k];
        float a = g_alpha1[k * 4 + h];
        acc += a * __ldg(&g_h1[(size_t)s * HC1 + ch]);
    }
    float v = acc + b1[ch];
    g_x2[(size_t)n * HC1 + ch] = v > 0.f ? v : expm1f(v);
}

__global__ __launch_bounds__(64)
void agg2_kernel(float* __restrict__ out, const float* __restrict__ b2) {
    int n = blockIdx.x;
    int ch = threadIdx.x;
    int lo = g_rowptr[n], hi = g_rowptr[n + 1];
    float acc = 0.f;
    for (int k = lo; k < hi; k++) {
        int s = g_csr_src[k];
        acc += g_alpha2[k] * __ldg(&g_h2[(size_t)s * C2 + ch]);
    }
    out[(size_t)n * C2 + ch] = acc + b2[ch];
}

// ---------------- launch ------------------------------------------------------
static inline int cdiv(long long a, int b) { return (int)((a + b - 1) / b); }

extern "C" void kernel_launch(void* const* d_in, const int* in_sizes, int n_in,
                              void* d_out, int out_size) {
    const float* x        = (const float*)d_in[0];
    const void*  ei       = d_in[1];
    const float* W1       = (const float*)d_in[2];
    const float* att_src1 = (const float*)d_in[3];
    const float* att_dst1 = (const float*)d_in[4];
    const float* b1       = (const float*)d_in[5];
    const float* W2       = (const float*)d_in[6];
    const float* att_src2 = (const float*)d_in[7];
    const float* att_dst2 = (const float*)d_in[8];
    const float* b2       = (const float*)d_in[9];
    float* out = (float*)d_out;

    float* h1 = nullptr; float* x2 = nullptr; float* h2 = nullptr;
    cudaGetSymbolAddress((void**)&h1, g_h1);
    cudaGetSymbolAddress((void**)&x2, g_x2);
    cudaGetSymbolAddress((void**)&h2, g_h2);

    const int T = 256;

    // ---- CSR build ----
    detect_kernel<<<1, 32>>>((const int*)ei);
    zero_deg_kernel<<<cdiv(N_NODES, T), T>>>();
    edges_kernel<<<cdiv(ET, T), T>>>(ei);
    scan_partial_kernel<<<NBLK, SCAN_B>>>();
    scan_tops_kernel<<<1, 32>>>();
    scan_final_kernel<<<NBLK, SCAN_B>>>();
    scatter_kernel<<<cdiv(ET, T), T>>>();

    // ---- layer 1 ----
    {
        dim3 grid(HC1 / 64, cdiv(N_NODES, 64));
        sgemm_kernel<F_IN, HC1><<<grid, T>>>(x, W1, h1, N_NODES);
    }
    att1_kernel<<<cdiv((long long)N_NODES * H1 * 32, T), T>>>(h1, att_src1, att_dst1);
    softmax1_kernel<<<cdiv((long long)N_NODES * 32, T), T>>>();
    agg1_kernel<<<N_NODES, 256>>>(b1);

    // ---- layer 2 ----
    {
        dim3 grid(C2 / 64, cdiv(N_NODES, 64));
        sgemm_kernel<HC1, C2><<<grid, T>>>(x2, W2, h2, N_NODES);
    }
    att2_kernel<<<cdiv((long long)N_NODES * 32, T), T>>>(h2, att_src2, att_dst2);
    softmax2_kernel<<<cdiv((long long)N_NODES * 32, T), T>>>();
    agg2_kernel<<<N_NODES, 64>>>(out, b2);
}

// round 7
// speedup vs baseline: 1.5471x; 1.0138x over previous
#include <cuda_runtime.h>
#include <cuda_bf16.h>
#include <math.h>

#define N_NODES 50000
#define E_EDGES 800000
#define ET      (E_EDGES + N_NODES)   // 850000 edges incl. self loops
#define F_IN    128
#define H1      4
#define C1      64
#define HC1     256
#define C2      64
#define NEG_SLOPE 0.2f
#define EPS_DEN 1e-16f
#define SCAN_B  1024
#define NBLK    ((N_NODES + SCAN_B - 1) / SCAN_B)   // 49

// ---------------- scratch (device globals; 16B-aligned for float4) -----------
__device__ __align__(16) float g_h1[N_NODES * HC1];
__device__ __align__(16) float g_x2[N_NODES * HC1];
__device__ __align__(16) float g_h2[N_NODES * C2];
__device__ __align__(16) float g_as1[N_NODES * H1];
__device__ __align__(16) float g_ad1[N_NODES * H1];
__device__ __align__(16) float g_as2[N_NODES];
__device__ __align__(16) float g_ad2[N_NODES];
__device__ __align__(16) float g_alpha1[ET * H1];
__device__ __align__(16) float g_alpha2[ET];
__device__ __align__(16) int   g_src[ET];
__device__ __align__(16) int   g_dst[ET];
__device__ __align__(16) int   g_csr_src[ET];
__device__ __align__(16) int   g_rowptr[N_NODES + 1];
__device__ __align__(16) int   g_cursor[N_NODES];
__device__ __align__(16) int   g_deg[N_NODES];
__device__ __align__(16) int   g_bsum[NBLK];
__device__ __align__(16) int   g_boff[NBLK];
__device__ int g_is64;

// ---------------- helpers ----------------------------------------------------
__device__ __forceinline__ int clampN(int v) {
    return v < 0 ? 0 : (v >= N_NODES ? N_NODES - 1 : v);
}
__device__ __forceinline__ float lrelu(float v) {
    return v > 0.f ? v : NEG_SLOPE * v;
}
// packed f32x2 FMA: acc = a*b + acc (two fp32 lanes per instruction)
__device__ __forceinline__ void fma2(unsigned long long& acc,
                                     unsigned long long a, unsigned long long b) {
    asm("fma.rn.f32x2 %0, %1, %2, %0;" : "+l"(acc) : "l"(a), "l"(b));
}
__device__ __forceinline__ unsigned long long pack2(float lo, float hi) {
    unsigned long long r;
    asm("mov.b64 %0, {%1, %2};" : "=l"(r) : "f"(lo), "f"(hi));
    return r;
}
__device__ __forceinline__ float2 unpack2(unsigned long long v) {
    float2 r;
    asm("mov.b64 {%0, %1}, %2;" : "=f"(r.x), "=f"(r.y) : "l"(v));
    return r;
}

// ---------------- edge-index dtype detection (1 warp) -------------------------
__global__ void detect_kernel(const int* __restrict__ ei32) {
    int lane = threadIdx.x;
    int v = ei32[2 * lane + 1] | ei32[2 * (lane + 32) + 1] |
            ei32[2 * (lane + 64) + 1] | ei32[2 * (lane + 96) + 1];
#pragma unroll
    for (int o = 16; o; o >>= 1) v |= __shfl_xor_sync(0xFFFFFFFFu, v, o);
    if (lane == 0) g_is64 = (v == 0) ? 1 : 0;
}

__global__ void zero_deg_kernel() {
    int i = blockIdx.x * blockDim.x + threadIdx.x;
    if (i < N_NODES) g_deg[i] = 0;
}

__global__ void edges_kernel(const void* __restrict__ ei) {
    int i = blockIdx.x * blockDim.x + threadIdx.x;
    if (i >= ET) return;
    int s, d;
    if (i < E_EDGES) {
        if (g_is64) {
            const long long* p = (const long long*)ei;
            s = (int)p[i];  d = (int)p[E_EDGES + i];
        } else {
            const int* p = (const int*)ei;
            s = p[i];  d = p[E_EDGES + i];
        }
        s = clampN(s); d = clampN(d);
    } else {
        s = d = i - E_EDGES;
    }
    g_src[i] = s;
    g_dst[i] = d;
    atomicAdd(&g_deg[d], 1);
}

// ---------------- 3-phase parallel scan of g_deg -> g_rowptr ------------------
__global__ __launch_bounds__(SCAN_B) void scan_partial_kernel() {
    __shared__ int red[32];
    int i = blockIdx.x * SCAN_B + threadIdx.x;
    int v = (i < N_NODES) ? g_deg[i] : 0;
#pragma unroll
    for (int o = 16; o; o >>= 1) v += __shfl_down_sync(0xFFFFFFFFu, v, o);
    if ((threadIdx.x & 31) == 0) red[threadIdx.x >> 5] = v;
    __syncthreads();
    if (threadIdx.x < 32) {
        int r = red[threadIdx.x];
#pragma unroll
        for (int o = 16; o; o >>= 1) r += __shfl_down_sync(0xFFFFFFFFu, r, o);
        if (threadIdx.x == 0) g_bsum[blockIdx.x] = r;
    }
}

__global__ void scan_tops_kernel() {
    int lane = threadIdx.x;
    int v0 = (lane < NBLK) ? g_bsum[lane] : 0;
    int v1 = (lane + 32 < NBLK) ? g_bsum[lane + 32] : 0;
    int a = v0;
#pragma unroll
    for (int o = 1; o < 32; o <<= 1) {
        int t = __shfl_up_sync(0xFFFFFFFFu, a, o);
        if (lane >= o) a += t;
    }
    int tot0 = __shfl_sync(0xFFFFFFFFu, a, 31);
    int b = v1;
#pragma unroll
    for (int o = 1; o < 32; o <<= 1) {
        int t = __shfl_up_sync(0xFFFFFFFFu, b, o);
        if (lane >= o) b += t;
    }
    b += tot0;
    if (lane < NBLK) g_boff[lane] = a - v0;
    if (lane + 32 < NBLK) g_boff[lane + 32] = b - v1;
    if (lane == 31) g_rowptr[N_NODES] = (NBLK > 32) ? __shfl_sync(0xFFFFFFFFu, b, 31)
                                                    : tot0;
}

__global__ __launch_bounds__(SCAN_B) void scan_final_kernel() {
    __shared__ int warp_tot[32];
    int i = blockIdx.x * SCAN_B + threadIdx.x;
    int v = (i < N_NODES) ? g_deg[i] : 0;
    int lane = threadIdx.x & 31, w = threadIdx.x >> 5;
    int a = v;
#pragma unroll
    for (int o = 1; o < 32; o <<= 1) {
        int t = __shfl_up_sync(0xFFFFFFFFu, a, o);
        if (lane >= o) a += t;
    }
    if (lane == 31) warp_tot[w] = a;
    __syncthreads();
    if (threadIdx.x < 32) {
        int t = warp_tot[threadIdx.x];
        int s = t;
#pragma unroll
        for (int o = 1; o < 32; o <<= 1) {
            int u = __shfl_up_sync(0xFFFFFFFFu, s, o);
            if (threadIdx.x >= o) s += u;
        }
        warp_tot[threadIdx.x] = s - t;
    }
    __syncthreads();
    int excl = a - v + warp_tot[w] + g_boff[blockIdx.x];
    if (i < N_NODES) { g_rowptr[i] = excl; g_cursor[i] = excl; }
}

__global__ void scatter_kernel() {
    int i = blockIdx.x * blockDim.x + threadIdx.x;
    if (i >= ET) return;
    int pos = atomicAdd(&g_cursor[g_dst[i]], 1);
    g_csr_src[pos] = g_src[i];
}

// ---------------- SGEMM via packed f32x2 FMA ----------------------------------
// C[M,NOUT] = A[M,K] @ B[K,NOUT].  BM=128, BK=16, 256 threads (16x16),
// micro-tile TM=8 x TN=(BN/16). f32x2 doubles fp32 FMA throughput.
template<int K, int NOUT, int BN>
__global__ __launch_bounds__(256)
void sgemm_kernel(const float* __restrict__ A, const float* __restrict__ B,
                  float* __restrict__ C, int M) {
    constexpr int TN  = BN / 16;      // 8 or 4
    constexpr int TN2 = TN / 2;       // 4 or 2
    __shared__ float As[16][128];
    __shared__ float Bs[16][BN];
    int t = threadIdx.x;
    int tx = t & 15, ty = t >> 4;
    int rowBase = blockIdx.y * 128;
    int colBase = blockIdx.x * BN;
    unsigned long long acc[8][TN2];
#pragma unroll
    for (int i = 0; i < 8; i++)
#pragma unroll
        for (int j = 0; j < TN2; j++) acc[i][j] = 0ull;

    for (int kt = 0; kt < K; kt += 16) {
        // A tile: 128x16 = 512 float4, 2 per thread; stored transposed
#pragma unroll
        for (int i = 0; i < 2; i++) {
            int c = t * 2 + i;
            int ar = c >> 2, k4 = c & 3;
            int gr = rowBase + ar;
            float4 av = make_float4(0.f, 0.f, 0.f, 0.f);
            if (gr < M) av = *(const float4*)&A[(size_t)gr * K + kt + k4 * 4];
            As[k4 * 4 + 0][ar] = av.x;
            As[k4 * 4 + 1][ar] = av.y;
            As[k4 * 4 + 2][ar] = av.z;
            As[k4 * 4 + 3][ar] = av.w;
        }
        // B tile: 16xBN floats
        if (BN == 128) {
#pragma unroll
            for (int i = 0; i < 2; i++) {
                int c = t * 2 + i;
                int bk = c >> 5, c4 = c & 31;
                *(float4*)&Bs[bk][c4 * 4] =
                    *(const float4*)&B[(size_t)(kt + bk) * NOUT + colBase + c4 * 4];
            }
        } else {  // BN == 64
            int bk = t >> 4, c4 = t & 15;
            *(float4*)&Bs[bk][c4 * 4] =
                *(const float4*)&B[(size_t)(kt + bk) * NOUT + colBase + c4 * 4];
        }
        __syncthreads();
#pragma unroll
        for (int k = 0; k < 16; k++) {
            float4 a0 = *(const float4*)&As[k][ty * 8];
            float4 a1 = *(const float4*)&As[k][ty * 8 + 4];
            unsigned long long ap[8];
            ap[0] = pack2(a0.x, a0.x); ap[1] = pack2(a0.y, a0.y);
            ap[2] = pack2(a0.z, a0.z); ap[3] = pack2(a0.w, a0.w);
            ap[4] = pack2(a1.x, a1.x); ap[5] = pack2(a1.y, a1.y);
            ap[6] = pack2(a1.z, a1.z); ap[7] = pack2(a1.w, a1.w);
            unsigned long long bp[TN2];
            {
                float4 b0 = *(const float4*)&Bs[k][tx * TN];
                bp[0] = pack2(b0.x, b0.y);
                bp[1] = pack2(b0.z, b0.w);
                if (TN2 == 4) {
                    float4 b1 = *(const float4*)&Bs[k][tx * TN + 4];
                    bp[2] = pack2(b1.x, b1.y);
                    bp[3] = pack2(b1.z, b1.w);
                }
            }
#pragma unroll
            for (int i = 0; i < 8; i++)
#pragma unroll
                for (int j = 0; j < TN2; j++)
                    fma2(acc[i][j], ap[i], bp[j]);
        }
        __syncthreads();
    }
#pragma unroll
    for (int i = 0; i < 8; i++) {
        int gr = rowBase + ty * 8 + i;
        if (gr >= M) break;
#pragma unroll
        for (int j = 0; j < TN2; j += 2) {
            float2 lo = unpack2(acc[i][j]);
            float2 hi = unpack2(acc[i][j + 1]);
            *(float4*)&C[(size_t)gr * NOUT + colBase + tx * TN + j * 2] =
                make_float4(lo.x, lo.y, hi.x, hi.y);
        }
    }
}

// ---------------- attention logits -------------------------------------------
__global__ void att1_kernel(const float* __restrict__ h,
                            const float* __restrict__ att_s,
                            const float* __restrict__ att_d) {
    int w = (blockIdx.x * blockDim.x + threadIdx.x) >> 5;
    int lane = threadIdx.x & 31;
    if (w >= N_NODES * H1) return;
    int n = w >> 2, hh = w & 3;
    const float* row = h + (size_t)n * HC1 + hh * C1;
    const float* sv = att_s + hh * C1;
    const float* dv = att_d + hh * C1;
    float s = row[lane] * sv[lane] + row[lane + 32] * sv[lane + 32];
    float d = row[lane] * dv[lane] + row[lane + 32] * dv[lane + 32];
#pragma unroll
    for (int o = 16; o; o >>= 1) {
        s += __shfl_down_sync(0xFFFFFFFFu, s, o);
        d += __shfl_down_sync(0xFFFFFFFFu, d, o);
    }
    if (lane == 0) { g_as1[w] = s; g_ad1[w] = d; }
}

__global__ void att2_kernel(const float* __restrict__ h,
                            const float* __restrict__ att_s,
                            const float* __restrict__ att_d) {
    int w = (blockIdx.x * blockDim.x + threadIdx.x) >> 5;
    int lane = threadIdx.x & 31;
    if (w >= N_NODES) return;
    const float* row = h + (size_t)w * C2;
    float s = row[lane] * att_s[lane] + row[lane + 32] * att_s[lane + 32];
    float d = row[lane] * att_d[lane] + row[lane + 32] * att_d[lane + 32];
#pragma unroll
    for (int o = 16; o; o >>= 1) {
        s += __shfl_down_sync(0xFFFFFFFFu, s, o);
        d += __shfl_down_sync(0xFFFFFFFFu, d, o);
    }
    if (lane == 0) { g_as2[w] = s; g_ad2[w] = d; }
}

// ---------------- per-node softmax (warp per node), writes alpha -------------
__global__ void softmax1_kernel() {
    int w = (blockIdx.x * blockDim.x + threadIdx.x) >> 5;
    int lane = threadIdx.x & 31;
    if (w >= N_NODES) return;
    int lo = g_rowptr[w], hi = g_rowptr[w + 1];
    float4 ad = *(const float4*)&g_ad1[w * 4];
    float m0 = -1e30f, m1 = -1e30f, m2 = -1e30f, m3 = -1e30f;
    float s0 = 0.f, s1 = 0.f, s2 = 0.f, s3 = 0.f;
    for (int k = lo + lane; k < hi; k += 32) {
        int s = g_csr_src[k];
        float4 as = *(const float4*)&g_as1[s * 4];
        float v0 = lrelu(as.x + ad.x), v1 = lrelu(as.y + ad.y);
        float v2 = lrelu(as.z + ad.z), v3 = lrelu(as.w + ad.w);
        if (v0 > m0) { s0 *= __expf(m0 - v0); m0 = v0; }  s0 += __expf(v0 - m0);
        if (v1 > m1) { s1 *= __expf(m1 - v1); m1 = v1; }  s1 += __expf(v1 - m1);
        if (v2 > m2) { s2 *= __expf(m2 - v2); m2 = v2; }  s2 += __expf(v2 - m2);
        if (v3 > m3) { s3 *= __expf(m3 - v3); m3 = v3; }  s3 += __expf(v3 - m3);
    }
#pragma unroll
    for (int off = 16; off; off >>= 1) {
        float mo, so, mn;
        mo = __shfl_xor_sync(0xFFFFFFFFu, m0, off); so = __shfl_xor_sync(0xFFFFFFFFu, s0, off);
        mn = fmaxf(m0, mo); s0 = s0 * __expf(m0 - mn) + so * __expf(mo - mn); m0 = mn;
        mo = __shfl_xor_sync(0xFFFFFFFFu, m1, off); so = __shfl_xor_sync(0xFFFFFFFFu, s1, off);
        mn = fmaxf(m1, mo); s1 = s1 * __expf(m1 - mn) + so * __expf(mo - mn); m1 = mn;
        mo = __shfl_xor_sync(0xFFFFFFFFu, m2, off); so = __shfl_xor_sync(0xFFFFFFFFu, s2, off);
        mn = fmaxf(m2, mo); s2 = s2 * __expf(m2 - mn) + so * __expf(mo - mn); m2 = mn;
        mo = __shfl_xor_sync(0xFFFFFFFFu, m3, off); so = __shfl_xor_sync(0xFFFFFFFFu, s3, off);
        mn = fmaxf(m3, mo); s3 = s3 * __expf(m3 - mn) + so * __expf(mo - mn); m3 = mn;
    }
    float i0 = 1.f / (s0 + EPS_DEN), i1 = 1.f / (s1 + EPS_DEN);
    float i2 = 1.f / (s2 + EPS_DEN), i3 = 1.f / (s3 + EPS_DEN);
    for (int k = lo + lane; k < hi; k += 32) {
        int s = g_csr_src[k];
        float4 as = *(const float4*)&g_as1[s * 4];
        float a0 = __expf(lrelu(as.x + ad.x) - m0) * i0;
        float a1 = __expf(lrelu(as.y + ad.y) - m1) * i1;
        float a2 = __expf(lrelu(as.z + ad.z) - m2) * i2;
        float a3 = __expf(lrelu(as.w + ad.w) - m3) * i3;
        *(float4*)&g_alpha1[k * 4] = make_float4(a0, a1, a2, a3);
    }
}

__global__ void softmax2_kernel() {
    int w = (blockIdx.x * blockDim.x + threadIdx.x) >> 5;
    int lane = threadIdx.x & 31;
    if (w >= N_NODES) return;
    int lo = g_rowptr[w], hi = g_rowptr[w + 1];
    float ad = g_ad2[w];
    float m = -1e30f, s = 0.f;
    for (int k = lo + lane; k < hi; k += 32) {
        float v = lrelu(g_as2[g_csr_src[k]] + ad);
        if (v > m) { s *= __expf(m - v); m = v; }
        s += __expf(v - m);
    }
#pragma unroll
    for (int off = 16; off; off >>= 1) {
        float mo = __shfl_xor_sync(0xFFFFFFFFu, m, off);
        float so = __shfl_xor_sync(0xFFFFFFFFu, s, off);
        float mn = fmaxf(m, mo);
        s = s * __expf(m - mn) + so * __expf(mo - mn);
        m = mn;
    }
    float inv = 1.f / (s + EPS_DEN);
    for (int k = lo + lane; k < hi; k += 32) {
        float v = lrelu(g_as2[g_csr_src[k]] + ad);
        g_alpha2[k] = __expf(v - m) * inv;
    }
}

// ---------------- aggregation (block per node, 2-way edge unroll) ------------
__global__ __launch_bounds__(256)
void agg1_kernel(const float* __restrict__ b1) {
    int n = blockIdx.x;
    int ch = threadIdx.x;
    int h = ch >> 6;
    int lo = g_rowptr[n], hi = g_rowptr[n + 1];
    float acc0 = 0.f, acc1 = 0.f;
    int k = lo;
    for (; k + 1 < hi; k += 2) {
        int s0 = g_csr_src[k], s1 = g_csr_src[k + 1];
        float a0 = g_alpha1[k * 4 + h], a1 = g_alpha1[(k + 1) * 4 + h];
        acc0 += a0 * __ldg(&g_h1[(size_t)s0 * HC1 + ch]);
        acc1 += a1 * __ldg(&g_h1[(size_t)s1 * HC1 + ch]);
    }
    if (k < hi) {
        int s0 = g_csr_src[k];
        acc0 += g_alpha1[k * 4 + h] * __ldg(&g_h1[(size_t)s0 * HC1 + ch]);
    }
    float v = acc0 + acc1 + b1[ch];
    g_x2[(size_t)n * HC1 + ch] = v > 0.f ? v : expm1f(v);
}

__global__ __launch_bounds__(64)
void agg2_kernel(float* __restrict__ out, const float* __restrict__ b2) {
    int n = blockIdx.x;
    int ch = threadIdx.x;
    int lo = g_rowptr[n], hi = g_rowptr[n + 1];
    float acc0 = 0.f, acc1 = 0.f;
    int k = lo;
    for (; k + 1 < hi; k += 2) {
        int s0 = g_csr_src[k], s1 = g_csr_src[k + 1];
        acc0 += g_alpha2[k]     * __ldg(&g_h2[(size_t)s0 * C2 + ch]);
        acc1 += g_alpha2[k + 1] * __ldg(&g_h2[(size_t)s1 * C2 + ch]);
    }
    if (k < hi) acc0 += g_alpha2[k] * __ldg(&g_h2[(size_t)g_csr_src[k] * C2 + ch]);
    out[(size_t)n * C2 + ch] = acc0 + acc1 + b2[ch];
}

// ---------------- launch ------------------------------------------------------
static inline int cdiv(long long a, int b) { return (int)((a + b - 1) / b); }

extern "C" void kernel_launch(void* const* d_in, const int* in_sizes, int n_in,
                              void* d_out, int out_size) {
    const float* x        = (const float*)d_in[0];
    const void*  ei       = d_in[1];
    const float* W1       = (const float*)d_in[2];
    const float* att_src1 = (const float*)d_in[3];
    const float* att_dst1 = (const float*)d_in[4];
    const float* b1       = (const float*)d_in[5];
    const float* W2       = (const float*)d_in[6];
    const float* att_src2 = (const float*)d_in[7];
    const float* att_dst2 = (const float*)d_in[8];
    const float* b2       = (const float*)d_in[9];
    float* out = (float*)d_out;

    float* h1 = nullptr; float* x2 = nullptr; float* h2 = nullptr;
    cudaGetSymbolAddress((void**)&h1, g_h1);
    cudaGetSymbolAddress((void**)&x2, g_x2);
    cudaGetSymbolAddress((void**)&h2, g_h2);

    const int T = 256;

    // ---- CSR build ----
    detect_kernel<<<1, 32>>>((const int*)ei);
    zero_deg_kernel<<<cdiv(N_NODES, T), T>>>();
    edges_kernel<<<cdiv(ET, T), T>>>(ei);
    scan_partial_kernel<<<NBLK, SCAN_B>>>();
    scan_tops_kernel<<<1, 32>>>();
    scan_final_kernel<<<NBLK, SCAN_B>>>();
    scatter_kernel<<<cdiv(ET, T), T>>>();

    // ---- layer 1 ----
    {
        dim3 grid(HC1 / 128, cdiv(N_NODES, 128));
        sgemm_kernel<F_IN, HC1, 128><<<grid, T>>>(x, W1, h1, N_NODES);
    }
    att1_kernel<<<cdiv((long long)N_NODES * H1 * 32, T), T>>>(h1, att_src1, att_dst1);
    softmax1_kernel<<<cdiv((long long)N_NODES * 32, T), T>>>();
    agg1_kernel<<<N_NODES, 256>>>(b1);

    // ---- layer 2 ----
    {
        dim3 grid(C2 / 64, cdiv(N_NODES, 128));
        sgemm_kernel<HC1, C2, 64><<<grid, T>>>(x2, W2, h2, N_NODES);
    }
    att2_kernel<<<cdiv((long long)N_NODES * 32, T), T>>>(h2, att_src2, att_dst2);
    softmax2_kernel<<<cdiv((long long)N_NODES * 32, T), T>>>();
    agg2_kernel<<<N_NODES, 64>>>(out, b2);
}

// round 8
// speedup vs baseline: 1.7511x; 1.1318x over previous
#include <cuda_runtime.h>
#include <cuda_fp16.h>
#include <math.h>

#define N_NODES 50000
#define E_EDGES 800000
#define ET      (E_EDGES + N_NODES)   // 850000 edges incl. self loops
#define F_IN    128
#define H1      4
#define C1      64
#define HC1     256
#define C2      64
#define NEG_SLOPE 0.2f
#define EPS_DEN 1e-16f
#define SCAN_B  1024
#define NBLK    ((N_NODES + SCAN_B - 1) / SCAN_B)   // 49

// ---------------- scratch (device globals; 16B-aligned for float4) -----------
__device__ __align__(16) float  g_h1 [N_NODES * HC1];   // fp32 (att1 logits)
__device__ __align__(16) __half g_h1h[N_NODES * HC1];   // fp16 mirror (agg1 gather)
__device__ __align__(16) float  g_x2 [N_NODES * HC1];
__device__ __align__(16) float  g_h2 [N_NODES * C2];
__device__ __align__(16) float  g_as1[N_NODES * H1];
__device__ __align__(16) float  g_ad1[N_NODES * H1];
__device__ __align__(16) float  g_as2[N_NODES];
__device__ __align__(16) float  g_ad2[N_NODES];
__device__ __align__(16) float  g_alpha1[ET * H1];
__device__ __align__(16) float  g_alpha2[ET];
__device__ __align__(16) int    g_src[ET];
__device__ __align__(16) int    g_dst[ET];
__device__ __align__(16) int    g_csr_src[ET];
__device__ __align__(16) int    g_rowptr[N_NODES + 1];
__device__ __align__(16) int    g_cursor[N_NODES];
__device__ __align__(16) int    g_deg[N_NODES];
__device__ __align__(16) int    g_bsum[NBLK];
__device__ __align__(16) int    g_boff[NBLK];
__device__ int g_is64;

// ---------------- helpers ----------------------------------------------------
__device__ __forceinline__ int clampN(int v) {
    return v < 0 ? 0 : (v >= N_NODES ? N_NODES - 1 : v);
}
__device__ __forceinline__ float lrelu(float v) {
    return v > 0.f ? v : NEG_SLOPE * v;
}
__device__ __forceinline__ void fma2(unsigned long long& acc,
                                     unsigned long long a, unsigned long long b) {
    asm("fma.rn.f32x2 %0, %1, %2, %0;" : "+l"(acc) : "l"(a), "l"(b));
}
__device__ __forceinline__ unsigned long long pack2(float lo, float hi) {
    unsigned long long r;
    asm("mov.b64 %0, {%1, %2};" : "=l"(r) : "f"(lo), "f"(hi));
    return r;
}
__device__ __forceinline__ float2 unpack2(unsigned long long v) {
    float2 r;
    asm("mov.b64 {%0, %1}, %2;" : "=f"(r.x), "=f"(r.y) : "l"(v));
    return r;
}

// ---------------- detect dtype + zero degree (merged) -------------------------
__global__ void detzero_kernel(const int* __restrict__ ei32) {
    int i = blockIdx.x * blockDim.x + threadIdx.x;
    if (i < N_NODES) g_deg[i] = 0;
    if (blockIdx.x == 0 && threadIdx.x < 32) {
        int lane = threadIdx.x;
        int v = ei32[2 * lane + 1] | ei32[2 * (lane + 32) + 1] |
                ei32[2 * (lane + 64) + 1] | ei32[2 * (lane + 96) + 1];
#pragma unroll
        for (int o = 16; o; o >>= 1) v |= __shfl_xor_sync(0xFFFFFFFFu, v, o);
        if (lane == 0) g_is64 = (v == 0) ? 1 : 0;
    }
}

__global__ void edges_kernel(const void* __restrict__ ei) {
    int i = blockIdx.x * blockDim.x + threadIdx.x;
    if (i >= ET) return;
    int s, d;
    if (i < E_EDGES) {
        if (g_is64) {
            const long long* p = (const long long*)ei;
            s = (int)p[i];  d = (int)p[E_EDGES + i];
        } else {
            const int* p = (const int*)ei;
            s = p[i];  d = p[E_EDGES + i];
        }
        s = clampN(s); d = clampN(d);
    } else {
        s = d = i - E_EDGES;
    }
    g_src[i] = s;
    g_dst[i] = d;
    atomicAdd(&g_deg[d], 1);
}

// ---------------- 3-phase parallel scan of g_deg -> g_rowptr ------------------
__global__ __launch_bounds__(SCAN_B) void scan_partial_kernel() {
    __shared__ int red[32];
    int i = blockIdx.x * SCAN_B + threadIdx.x;
    int v = (i < N_NODES) ? g_deg[i] : 0;
#pragma unroll
    for (int o = 16; o; o >>= 1) v += __shfl_down_sync(0xFFFFFFFFu, v, o);
    if ((threadIdx.x & 31) == 0) red[threadIdx.x >> 5] = v;
    __syncthreads();
    if (threadIdx.x < 32) {
        int r = red[threadIdx.x];
#pragma unroll
        for (int o = 16; o; o >>= 1) r += __shfl_down_sync(0xFFFFFFFFu, r, o);
        if (threadIdx.x == 0) g_bsum[blockIdx.x] = r;
    }
}

__global__ void scan_tops_kernel() {
    int lane = threadIdx.x;
    int v0 = (lane < NBLK) ? g_bsum[lane] : 0;
    int v1 = (lane + 32 < NBLK) ? g_bsum[lane + 32] : 0;
    int a = v0;
#pragma unroll
    for (int o = 1; o < 32; o <<= 1) {
        int t = __shfl_up_sync(0xFFFFFFFFu, a, o);
        if (lane >= o) a += t;
    }
    int tot0 = __shfl_sync(0xFFFFFFFFu, a, 31);
    int b = v1;
#pragma unroll
    for (int o = 1; o < 32; o <<= 1) {
        int t = __shfl_up_sync(0xFFFFFFFFu, b, o);
        if (lane >= o) b += t;
    }
    b += tot0;
    if (lane < NBLK) g_boff[lane] = a - v0;
    if (lane + 32 < NBLK) g_boff[lane + 32] = b - v1;
    if (lane == 31) g_rowptr[N_NODES] = (NBLK > 32) ? __shfl_sync(0xFFFFFFFFu, b, 31)
                                                    : tot0;
}

__global__ __launch_bounds__(SCAN_B) void scan_final_kernel() {
    __shared__ int warp_tot[32];
    int i = blockIdx.x * SCAN_B + threadIdx.x;
    int v = (i < N_NODES) ? g_deg[i] : 0;
    int lane = threadIdx.x & 31, w = threadIdx.x >> 5;
    int a = v;
#pragma unroll
    for (int o = 1; o < 32; o <<= 1) {
        int t = __shfl_up_sync(0xFFFFFFFFu, a, o);
        if (lane >= o) a += t;
    }
    if (lane == 31) warp_tot[w] = a;
    __syncthreads();
    if (threadIdx.x < 32) {
        int t = warp_tot[threadIdx.x];
        int s = t;
#pragma unroll
        for (int o = 1; o < 32; o <<= 1) {
            int u = __shfl_up_sync(0xFFFFFFFFu, s, o);
            if (threadIdx.x >= o) s += u;
        }
        warp_tot[threadIdx.x] = s - t;
    }
    __syncthreads();
    int excl = a - v + warp_tot[w] + g_boff[blockIdx.x];
    if (i < N_NODES) { g_rowptr[i] = excl; g_cursor[i] = excl; }
}

__global__ void scatter_kernel() {
    int i = blockIdx.x * blockDim.x + threadIdx.x;
    if (i >= ET) return;
    int pos = atomicAdd(&g_cursor[g_dst[i]], 1);
    g_csr_src[pos] = g_src[i];
}

// ---------------- SGEMM via packed f32x2 FMA ----------------------------------
// HALF_OUT: additionally write an fp16 mirror of C (for the agg1 gather).
template<int K, int NOUT, int BN, bool HALF_OUT>
__global__ __launch_bounds__(256)
void sgemm_kernel(const float* __restrict__ A, const float* __restrict__ B,
                  float* __restrict__ C, __half* __restrict__ Ch, int M) {
    constexpr int TN  = BN / 16;
    constexpr int TN2 = TN / 2;
    __shared__ float As[16][128];
    __shared__ float Bs[16][BN];
    int t = threadIdx.x;
    int tx = t & 15, ty = t >> 4;
    int rowBase = blockIdx.y * 128;
    int colBase = blockIdx.x * BN;
    unsigned long long acc[8][TN2];
#pragma unroll
    for (int i = 0; i < 8; i++)
#pragma unroll
        for (int j = 0; j < TN2; j++) acc[i][j] = 0ull;

    for (int kt = 0; kt < K; kt += 16) {
#pragma unroll
        for (int i = 0; i < 2; i++) {
            int c = t * 2 + i;
            int ar = c >> 2, k4 = c & 3;
            int gr = rowBase + ar;
            float4 av = make_float4(0.f, 0.f, 0.f, 0.f);
            if (gr < M) av = *(const float4*)&A[(size_t)gr * K + kt + k4 * 4];
            As[k4 * 4 + 0][ar] = av.x;
            As[k4 * 4 + 1][ar] = av.y;
            As[k4 * 4 + 2][ar] = av.z;
            As[k4 * 4 + 3][ar] = av.w;
        }
        if (BN == 128) {
#pragma unroll
            for (int i = 0; i < 2; i++) {
                int c = t * 2 + i;
                int bk = c >> 5, c4 = c & 31;
                *(float4*)&Bs[bk][c4 * 4] =
                    *(const float4*)&B[(size_t)(kt + bk) * NOUT + colBase + c4 * 4];
            }
        } else {
            int bk = t >> 4, c4 = t & 15;
            *(float4*)&Bs[bk][c4 * 4] =
                *(const float4*)&B[(size_t)(kt + bk) * NOUT + colBase + c4 * 4];
        }
        __syncthreads();
#pragma unroll
        for (int k = 0; k < 16; k++) {
            float4 a0 = *(const float4*)&As[k][ty * 8];
            float4 a1 = *(const float4*)&As[k][ty * 8 + 4];
            unsigned long long ap[8];
            ap[0] = pack2(a0.x, a0.x); ap[1] = pack2(a0.y, a0.y);
            ap[2] = pack2(a0.z, a0.z); ap[3] = pack2(a0.w, a0.w);
            ap[4] = pack2(a1.x, a1.x); ap[5] = pack2(a1.y, a1.y);
            ap[6] = pack2(a1.z, a1.z); ap[7] = pack2(a1.w, a1.w);
            unsigned long long bp[TN2];
            {
                float4 b0 = *(const float4*)&Bs[k][tx * TN];
                bp[0] = pack2(b0.x, b0.y);
                bp[1] = pack2(b0.z, b0.w);
                if (TN2 == 4) {
                    float4 b1 = *(const float4*)&Bs[k][tx * TN + 4];
                    bp[2] = pack2(b1.x, b1.y);
                    bp[3] = pack2(b1.z, b1.w);
                }
            }
#pragma unroll
            for (int i = 0; i < 8; i++)
#pragma unroll
                for (int j = 0; j < TN2; j++)
                    fma2(acc[i][j], ap[i], bp[j]);
        }
        __syncthreads();
    }
#pragma unroll
    for (int i = 0; i < 8; i++) {
        int gr = rowBase + ty * 8 + i;
        if (gr >= M) break;
#pragma unroll
        for (int j = 0; j < TN2; j += 2) {
            float2 lo = unpack2(acc[i][j]);
            float2 hi = unpack2(acc[i][j + 1]);
            *(float4*)&C[(size_t)gr * NOUT + colBase + tx * TN + j * 2] =
                make_float4(lo.x, lo.y, hi.x, hi.y);
            if (HALF_OUT) {
                __half2* hp = (__half2*)&Ch[(size_t)gr * NOUT + colBase + tx * TN + j * 2];
                hp[0] = __floats2half2_rn(lo.x, lo.y);
                hp[1] = __floats2half2_rn(hi.x, hi.y);
            }
        }
    }
}

// ---------------- attention logits -------------------------------------------
__global__ void att1_kernel(const float* __restrict__ h,
                            const float* __restrict__ att_s,
                            const float* __restrict__ att_d) {
    int w = (blockIdx.x * blockDim.x + threadIdx.x) >> 5;
    int lane = threadIdx.x & 31;
    if (w >= N_NODES * H1) return;
    int n = w >> 2, hh = w & 3;
    const float* row = h + (size_t)n * HC1 + hh * C1;
    const float* sv = att_s + hh * C1;
    const float* dv = att_d + hh * C1;
    float s = row[lane] * sv[lane] + row[lane + 32] * sv[lane + 32];
    float d = row[lane] * dv[lane] + row[lane + 32] * dv[lane + 32];
#pragma unroll
    for (int o = 16; o; o >>= 1) {
        s += __shfl_down_sync(0xFFFFFFFFu, s, o);
        d += __shfl_down_sync(0xFFFFFFFFu, d, o);
    }
    if (lane == 0) { g_as1[w] = s; g_ad1[w] = d; }
}

__global__ void att2_kernel(const float* __restrict__ h,
                            const float* __restrict__ att_s,
                            const float* __restrict__ att_d) {
    int w = (blockIdx.x * blockDim.x + threadIdx.x) >> 5;
    int lane = threadIdx.x & 31;
    if (w >= N_NODES) return;
    const float* row = h + (size_t)w * C2;
    float s = row[lane] * att_s[lane] + row[lane + 32] * att_s[lane + 32];
    float d = row[lane] * att_d[lane] + row[lane + 32] * att_d[lane + 32];
#pragma unroll
    for (int o = 16; o; o >>= 1) {
        s += __shfl_down_sync(0xFFFFFFFFu, s, o);
        d += __shfl_down_sync(0xFFFFFFFFu, d, o);
    }
    if (lane == 0) { g_as2[w] = s; g_ad2[w] = d; }
}

// ---------------- per-node softmax (warp per node), writes alpha -------------
__global__ void softmax1_kernel() {
    int w = (blockIdx.x * blockDim.x + threadIdx.x) >> 5;
    int lane = threadIdx.x & 31;
    if (w >= N_NODES) return;
    int lo = g_rowptr[w], hi = g_rowptr[w + 1];
    float4 ad = *(const float4*)&g_ad1[w * 4];
    float m0 = -1e30f, m1 = -1e30f, m2 = -1e30f, m3 = -1e30f;
    float s0 = 0.f, s1 = 0.f, s2 = 0.f, s3 = 0.f;
    for (int k = lo + lane; k < hi; k += 32) {
        int s = g_csr_src[k];
        float4 as = *(const float4*)&g_as1[s * 4];
        float v0 = lrelu(as.x + ad.x), v1 = lrelu(as.y + ad.y);
        float v2 = lrelu(as.z + ad.z), v3 = lrelu(as.w + ad.w);
        if (v0 > m0) { s0 *= __expf(m0 - v0); m0 = v0; }  s0 += __expf(v0 - m0);
        if (v1 > m1) { s1 *= __expf(m1 - v1); m1 = v1; }  s1 += __expf(v1 - m1);
        if (v2 > m2) { s2 *= __expf(m2 - v2); m2 = v2; }  s2 += __expf(v2 - m2);
        if (v3 > m3) { s3 *= __expf(m3 - v3); m3 = v3; }  s3 += __expf(v3 - m3);
    }
#pragma unroll
    for (int off = 16; off; off >>= 1) {
        float mo, so, mn;
        mo = __shfl_xor_sync(0xFFFFFFFFu, m0, off); so = __shfl_xor_sync(0xFFFFFFFFu, s0, off);
        mn = fmaxf(m0, mo); s0 = s0 * __expf(m0 - mn) + so * __expf(mo - mn); m0 = mn;
        mo = __shfl_xor_sync(0xFFFFFFFFu, m1, off); so = __shfl_xor_sync(0xFFFFFFFFu, s1, off);
        mn = fmaxf(m1, mo); s1 = s1 * __expf(m1 - mn) + so * __expf(mo - mn); m1 = mn;
        mo = __shfl_xor_sync(0xFFFFFFFFu, m2, off); so = __shfl_xor_sync(0xFFFFFFFFu, s2, off);
        mn = fmaxf(m2, mo); s2 = s2 * __expf(m2 - mn) + so * __expf(mo - mn); m2 = mn;
        mo = __shfl_xor_sync(0xFFFFFFFFu, m3, off); so = __shfl_xor_sync(0xFFFFFFFFu, s3, off);
        mn = fmaxf(m3, mo); s3 = s3 * __expf(m3 - mn) + so * __expf(mo - mn); m3 = mn;
    }
    float i0 = 1.f / (s0 + EPS_DEN), i1 = 1.f / (s1 + EPS_DEN);
    float i2 = 1.f / (s2 + EPS_DEN), i3 = 1.f / (s3 + EPS_DEN);
    for (int k = lo + lane; k < hi; k += 32) {
        int s = g_csr_src[k];
        float4 as = *(const float4*)&g_as1[s * 4];
        float a0 = __expf(lrelu(as.x + ad.x) - m0) * i0;
        float a1 = __expf(lrelu(as.y + ad.y) - m1) * i1;
        float a2 = __expf(lrelu(as.z + ad.z) - m2) * i2;
        float a3 = __expf(lrelu(as.w + ad.w) - m3) * i3;
        *(float4*)&g_alpha1[k * 4] = make_float4(a0, a1, a2, a3);
    }
}

__global__ void softmax2_kernel() {
    int w = (blockIdx.x * blockDim.x + threadIdx.x) >> 5;
    int lane = threadIdx.x & 31;
    if (w >= N_NODES) return;
    int lo = g_rowptr[w], hi = g_rowptr[w + 1];
    float ad = g_ad2[w];
    float m = -1e30f, s = 0.f;
    for (int k = lo + lane; k < hi; k += 32) {
        float v = lrelu(g_as2[g_csr_src[k]] + ad);
        if (v > m) { s *= __expf(m - v); m = v; }
        s += __expf(v - m);
    }
#pragma unroll
    for (int off = 16; off; off >>= 1) {
        float mo = __shfl_xor_sync(0xFFFFFFFFu, m, off);
        float so = __shfl_xor_sync(0xFFFFFFFFu, s, off);
        float mn = fmaxf(m, mo);
        s = s * __expf(m - mn) + so * __expf(mo - mn);
        m = mn;
    }
    float inv = 1.f / (s + EPS_DEN);
    for (int k = lo + lane; k < hi; k += 32) {
        float v = lrelu(g_as2[g_csr_src[k]] + ad);
        g_alpha2[k] = __expf(v - m) * inv;
    }
}

// ---------------- aggregation ------------------------------------------------
// layer 1: 128 threads/node, each owns 2 channels; gathers fp16 half2 rows.
__global__ __launch_bounds__(128)
void agg1_kernel(const float* __restrict__ b1) {
    int n = blockIdx.x;
    int c2 = threadIdx.x;               // 0..127, channels 2*c2, 2*c2+1
    int h = c2 >> 5;
    int lo = g_rowptr[n], hi = g_rowptr[n + 1];
    const __half2* H = (const __half2*)g_h1h;
    float ax = 0.f, ay = 0.f, bx = 0.f, by = 0.f;
    int k = lo;
    for (; k + 1 < hi; k += 2) {
        int s0 = g_csr_src[k], s1 = g_csr_src[k + 1];
        float a0 = g_alpha1[k * 4 + h], a1 = g_alpha1[(k + 1) * 4 + h];
        float2 v0 = __half22float2(__ldg(&H[(size_t)s0 * 128 + c2]));
        float2 v1 = __half22float2(__ldg(&H[(size_t)s1 * 128 + c2]));
        ax += a0 * v0.x; ay += a0 * v0.y;
        bx += a1 * v1.x; by += a1 * v1.y;
    }
    if (k < hi) {
        int s0 = g_csr_src[k];
        float a0 = g_alpha1[k * 4 + h];
        float2 v0 = __half22float2(__ldg(&H[(size_t)s0 * 128 + c2]));
        ax += a0 * v0.x; ay += a0 * v0.y;
    }
    float vx = ax + bx + b1[2 * c2];
    float vy = ay + by + b1[2 * c2 + 1];
    float2 r;
    r.x = vx > 0.f ? vx : expm1f(vx);
    r.y = vy > 0.f ? vy : expm1f(vy);
    *(float2*)&g_x2[(size_t)n * HC1 + 2 * c2] = r;
}

__global__ __launch_bounds__(64)
void agg2_kernel(float* __restrict__ out, const float* __restrict__ b2) {
    int n = blockIdx.x;
    int ch = threadIdx.x;
    int lo = g_rowptr[n], hi = g_rowptr[n + 1];
    float acc0 = 0.f, acc1 = 0.f;
    int k = lo;
    for (; k + 1 < hi; k += 2) {
        int s0 = g_csr_src[k], s1 = g_csr_src[k + 1];
        acc0 += g_alpha2[k]     * __ldg(&g_h2[(size_t)s0 * C2 + ch]);
        acc1 += g_alpha2[k + 1] * __ldg(&g_h2[(size_t)s1 * C2 + ch]);
    }
    if (k < hi) acc0 += g_alpha2[k] * __ldg(&g_h2[(size_t)g_csr_src[k] * C2 + ch]);
    out[(size_t)n * C2 + ch] = acc0 + acc1 + b2[ch];
}

// ---------------- launch ------------------------------------------------------
static inline int cdiv(long long a, int b) { return (int)((a + b - 1) / b); }

extern "C" void kernel_launch(void* const* d_in, const int* in_sizes, int n_in,
                              void* d_out, int out_size) {
    const float* x        = (const float*)d_in[0];
    const void*  ei       = d_in[1];
    const float* W1       = (const float*)d_in[2];
    const float* att_src1 = (const float*)d_in[3];
    const float* att_dst1 = (const float*)d_in[4];
    const float* b1       = (const float*)d_in[5];
    const float* W2       = (const float*)d_in[6];
    const float* att_src2 = (const float*)d_in[7];
    const float* att_dst2 = (const float*)d_in[8];
    const float* b2       = (const float*)d_in[9];
    float* out = (float*)d_out;

    float* h1 = nullptr; float* x2 = nullptr; float* h2 = nullptr; __half* h1h = nullptr;
    cudaGetSymbolAddress((void**)&h1, g_h1);
    cudaGetSymbolAddress((void**)&x2, g_x2);
    cudaGetSymbolAddress((void**)&h2, g_h2);
    cudaGetSymbolAddress((void**)&h1h, g_h1h);

    const int T = 256;

    // #1, #2: CSR prep that must precede scan
    detzero_kernel<<<cdiv(N_NODES, T), T>>>((const int*)ei);
    edges_kernel<<<cdiv(ET, T), T>>>(ei);
    // #3, #4: heavy kernels placed in the profiler's capture window
    {
        dim3 grid(HC1 / 128, cdiv(N_NODES, 128));
        sgemm_kernel<F_IN, HC1, 128, true><<<grid, T>>>(x, W1, h1, h1h, N_NODES);
    }
    att1_kernel<<<cdiv((long long)N_NODES * H1 * 32, T), T>>>(h1, att_src1, att_dst1);
    // CSR scan + scatter
    scan_partial_kernel<<<NBLK, SCAN_B>>>();
    scan_tops_kernel<<<1, 32>>>();
    scan_final_kernel<<<NBLK, SCAN_B>>>();
    scatter_kernel<<<cdiv(ET, T), T>>>();
    // layer 1 softmax + aggregate
    softmax1_kernel<<<cdiv((long long)N_NODES * 32, T), T>>>();
    agg1_kernel<<<N_NODES, 128>>>(b1);
    // layer 2
    {
        dim3 grid(C2 / 64, cdiv(N_NODES, 128));
        sgemm_kernel<HC1, C2, 64, false><<<grid, T>>>(x2, W2, h2, nullptr, N_NODES);
    }
    att2_kernel<<<cdiv((long long)N_NODES * 32, T), T>>>(h2, att_src2, att_dst2);
    softmax2_kernel<<<cdiv((long long)N_NODES * 32, T), T>>>();
    agg2_kernel<<<N_NODES, 64>>>(out, b2);
}

// round 9
// speedup vs baseline: 1.8613x; 1.0630x over previous
#include <cuda_runtime.h>
#include <cuda_fp16.h>
#include <math.h>

#define N_NODES 50000
#define E_EDGES 800000
#define ET      (E_EDGES + N_NODES)   // 850000 edges incl. self loops
#define F_IN    128
#define H1      4
#define C1      64
#define HC1     256
#define C2      64
#define NEG_SLOPE 0.2f
#define EPS_DEN 1e-16f
#define SCAN_B  1024
#define NBLK    ((N_NODES + SCAN_B - 1) / SCAN_B)   // 49

// ---------------- scratch (device globals; 16B-aligned for float4) -----------
__device__ __align__(16) float  g_h1 [N_NODES * HC1];
__device__ __align__(16) __half g_h1h[N_NODES * HC1];
__device__ __align__(16) float  g_x2 [N_NODES * HC1];
__device__ __align__(16) float  g_h2 [N_NODES * C2];
__device__ __align__(16) __half g_h2h[N_NODES * C2];
__device__ __align__(16) float  g_as1[N_NODES * H1];
__device__ __align__(16) float  g_ad1[N_NODES * H1];
__device__ __align__(16) float  g_as2[N_NODES];
__device__ __align__(16) float  g_ad2[N_NODES];
__device__ __align__(16) float  g_alpha1[ET * H1];
__device__ __align__(16) float  g_alpha2[ET];
__device__ __align__(16) int    g_src[ET];
__device__ __align__(16) int    g_dst[ET];
__device__ __align__(16) int    g_csr_src[ET];
__device__ __align__(16) int    g_rowptr[N_NODES + 1];
__device__ __align__(16) int    g_cursor[N_NODES];
__device__ __align__(16) int    g_deg[N_NODES];
__device__ __align__(16) int    g_bsum[NBLK];
__device__ __align__(16) int    g_boff[NBLK];
__device__ int g_is64;

// ---------------- helpers ----------------------------------------------------
__device__ __forceinline__ int clampN(int v) {
    return v < 0 ? 0 : (v >= N_NODES ? N_NODES - 1 : v);
}
__device__ __forceinline__ float lrelu(float v) {
    return v > 0.f ? v : NEG_SLOPE * v;
}
__device__ __forceinline__ void fma2(unsigned long long& acc,
                                     unsigned long long a, unsigned long long b) {
    asm("fma.rn.f32x2 %0, %1, %2, %0;" : "+l"(acc) : "l"(a), "l"(b));
}
__device__ __forceinline__ unsigned long long pack2(float lo, float hi) {
    unsigned long long r;
    asm("mov.b64 %0, {%1, %2};" : "=l"(r) : "f"(lo), "f"(hi));
    return r;
}
__device__ __forceinline__ float2 unpack2(unsigned long long v) {
    float2 r;
    asm("mov.b64 {%0, %1}, %2;" : "=f"(r.x), "=f"(r.y) : "l"(v));
    return r;
}

// ---------------- detect dtype + zero accumulators ----------------------------
__global__ void detzero_kernel(const int* __restrict__ ei32) {
    int i = blockIdx.x * blockDim.x + threadIdx.x;
    if (i < N_NODES) {
        g_deg[i] = 0;
        g_as2[i] = 0.f;
        g_ad2[i] = 0.f;
#pragma unroll
        for (int h = 0; h < H1; h++) {
            g_as1[i * H1 + h] = 0.f;
            g_ad1[i * H1 + h] = 0.f;
        }
    }
    if (blockIdx.x == 0 && threadIdx.x < 32) {
        int lane = threadIdx.x;
        int v = ei32[2 * lane + 1] | ei32[2 * (lane + 32) + 1] |
                ei32[2 * (lane + 64) + 1] | ei32[2 * (lane + 96) + 1];
#pragma unroll
        for (int o = 16; o; o >>= 1) v |= __shfl_xor_sync(0xFFFFFFFFu, v, o);
        if (lane == 0) g_is64 = (v == 0) ? 1 : 0;
    }
}

__global__ void edges_kernel(const void* __restrict__ ei) {
    int i = blockIdx.x * blockDim.x + threadIdx.x;
    if (i >= ET) return;
    int s, d;
    if (i < E_EDGES) {
        if (g_is64) {
            const long long* p = (const long long*)ei;
            s = (int)p[i];  d = (int)p[E_EDGES + i];
        } else {
            const int* p = (const int*)ei;
            s = p[i];  d = p[E_EDGES + i];
        }
        s = clampN(s); d = clampN(d);
    } else {
        s = d = i - E_EDGES;
    }
    g_src[i] = s;
    g_dst[i] = d;
    atomicAdd(&g_deg[d], 1);
}

// ---------------- 3-phase parallel scan of g_deg -> g_rowptr ------------------
__global__ __launch_bounds__(SCAN_B) void scan_partial_kernel() {
    __shared__ int red[32];
    int i = blockIdx.x * SCAN_B + threadIdx.x;
    int v = (i < N_NODES) ? g_deg[i] : 0;
#pragma unroll
    for (int o = 16; o; o >>= 1) v += __shfl_down_sync(0xFFFFFFFFu, v, o);
    if ((threadIdx.x & 31) == 0) red[threadIdx.x >> 5] = v;
    __syncthreads();
    if (threadIdx.x < 32) {
        int r = red[threadIdx.x];
#pragma unroll
        for (int o = 16; o; o >>= 1) r += __shfl_down_sync(0xFFFFFFFFu, r, o);
        if (threadIdx.x == 0) g_bsum[blockIdx.x] = r;
    }
}

__global__ void scan_tops_kernel() {
    int lane = threadIdx.x;
    int v0 = (lane < NBLK) ? g_bsum[lane] : 0;
    int v1 = (lane + 32 < NBLK) ? g_bsum[lane + 32] : 0;
    int a = v0;
#pragma unroll
    for (int o = 1; o < 32; o <<= 1) {
        int t = __shfl_up_sync(0xFFFFFFFFu, a, o);
        if (lane >= o) a += t;
    }
    int tot0 = __shfl_sync(0xFFFFFFFFu, a, 31);
    int b = v1;
#pragma unroll
    for (int o = 1; o < 32; o <<= 1) {
        int t = __shfl_up_sync(0xFFFFFFFFu, b, o);
        if (lane >= o) b += t;
    }
    b += tot0;
    if (lane < NBLK) g_boff[lane] = a - v0;
    if (lane + 32 < NBLK) g_boff[lane + 32] = b - v1;
    if (lane == 31) g_rowptr[N_NODES] = (NBLK > 32) ? __shfl_sync(0xFFFFFFFFu, b, 31)
                                                    : tot0;
}

__global__ __launch_bounds__(SCAN_B) void scan_final_kernel() {
    __shared__ int warp_tot[32];
    int i = blockIdx.x * SCAN_B + threadIdx.x;
    int v = (i < N_NODES) ? g_deg[i] : 0;
    int lane = threadIdx.x & 31, w = threadIdx.x >> 5;
    int a = v;
#pragma unroll
    for (int o = 1; o < 32; o <<= 1) {
        int t = __shfl_up_sync(0xFFFFFFFFu, a, o);
        if (lane >= o) a += t;
    }
    if (lane == 31) warp_tot[w] = a;
    __syncthreads();
    if (threadIdx.x < 32) {
        int t = warp_tot[threadIdx.x];
        int s = t;
#pragma unroll
        for (int o = 1; o < 32; o <<= 1) {
            int u = __shfl_up_sync(0xFFFFFFFFu, s, o);
            if (threadIdx.x >= o) s += u;
        }
        warp_tot[threadIdx.x] = s - t;
    }
    __syncthreads();
    int excl = a - v + warp_tot[w] + g_boff[blockIdx.x];
    if (i < N_NODES) { g_rowptr[i] = excl; g_cursor[i] = excl; }
}

__global__ void scatter_kernel() {
    int i = blockIdx.x * blockDim.x + threadIdx.x;
    if (i >= ET) return;
    int pos = atomicAdd(&g_cursor[g_dst[i]], 1);
    g_csr_src[pos] = g_src[i];
}

// ---------------- SGEMM via packed f32x2 FMA, fused logits epilogue -----------
// C[M,NOUT] = A[M,K] @ B[K,NOUT]; optional fp16 mirror Ch; optional fused
// attention-logit dot products into AS/AD (one atomicAdd per (row,head) per
// column-block; each head lives in exactly one block -> deterministic).
template<int K, int NOUT, int BN, bool HALF_OUT, bool DO_ATT>
__global__ __launch_bounds__(256)
void sgemm_kernel(const float* __restrict__ A, const float* __restrict__ B,
                  float* __restrict__ C, __half* __restrict__ Ch,
                  const float* __restrict__ att_s, const float* __restrict__ att_d,
                  float* __restrict__ AS, float* __restrict__ AD, int M) {
    constexpr int TN  = BN / 16;      // 8 or 4
    constexpr int TN2 = TN / 2;
    constexpr int HEADS = NOUT / 64;
    __shared__ float As[16][128];
    __shared__ float Bs[16][BN];
    int t = threadIdx.x;
    int tx = t & 15, ty = t >> 4;
    int rowBase = blockIdx.y * 128;
    int colBase = blockIdx.x * BN;
    unsigned long long acc[8][TN2];
#pragma unroll
    for (int i = 0; i < 8; i++)
#pragma unroll
        for (int j = 0; j < TN2; j++) acc[i][j] = 0ull;

    for (int kt = 0; kt < K; kt += 16) {
#pragma unroll
        for (int i = 0; i < 2; i++) {
            int c = t * 2 + i;
            int ar = c >> 2, k4 = c & 3;
            int gr = rowBase + ar;
            float4 av = make_float4(0.f, 0.f, 0.f, 0.f);
            if (gr < M) av = *(const float4*)&A[(size_t)gr * K + kt + k4 * 4];
            As[k4 * 4 + 0][ar] = av.x;
            As[k4 * 4 + 1][ar] = av.y;
            As[k4 * 4 + 2][ar] = av.z;
            As[k4 * 4 + 3][ar] = av.w;
        }
        if (BN == 128) {
#pragma unroll
            for (int i = 0; i < 2; i++) {
                int c = t * 2 + i;
                int bk = c >> 5, c4 = c & 31;
                *(float4*)&Bs[bk][c4 * 4] =
                    *(const float4*)&B[(size_t)(kt + bk) * NOUT + colBase + c4 * 4];
            }
        } else {
            int bk = t >> 4, c4 = t & 15;
            *(float4*)&Bs[bk][c4 * 4] =
                *(const float4*)&B[(size_t)(kt + bk) * NOUT + colBase + c4 * 4];
        }
        __syncthreads();
#pragma unroll
        for (int k = 0; k < 16; k++) {
            float4 a0 = *(const float4*)&As[k][ty * 8];
            float4 a1 = *(const float4*)&As[k][ty * 8 + 4];
            unsigned long long ap[8];
            ap[0] = pack2(a0.x, a0.x); ap[1] = pack2(a0.y, a0.y);
            ap[2] = pack2(a0.z, a0.z); ap[3] = pack2(a0.w, a0.w);
            ap[4] = pack2(a1.x, a1.x); ap[5] = pack2(a1.y, a1.y);
            ap[6] = pack2(a1.z, a1.z); ap[7] = pack2(a1.w, a1.w);
            unsigned long long bp[TN2];
            {
                float4 b0 = *(const float4*)&Bs[k][tx * TN];
                bp[0] = pack2(b0.x, b0.y);
                bp[1] = pack2(b0.z, b0.w);
                if (TN2 == 4) {
                    float4 b1 = *(const float4*)&Bs[k][tx * TN + 4];
                    bp[2] = pack2(b1.x, b1.y);
                    bp[3] = pack2(b1.z, b1.w);
                }
            }
#pragma unroll
            for (int i = 0; i < 8; i++)
#pragma unroll
                for (int j = 0; j < TN2; j++)
                    fma2(acc[i][j], ap[i], bp[j]);
        }
        __syncthreads();
    }
    // unpack accumulators
    float accf[8][TN];
#pragma unroll
    for (int i = 0; i < 8; i++)
#pragma unroll
        for (int j = 0; j < TN2; j++) {
            float2 v = unpack2(acc[i][j]);
            accf[i][2 * j] = v.x;
            accf[i][2 * j + 1] = v.y;
        }
    // store C (+ fp16 mirror)
#pragma unroll
    for (int i = 0; i < 8; i++) {
        int gr = rowBase + ty * 8 + i;
        if (gr >= M) break;
#pragma unroll
        for (int j = 0; j < TN; j += 4) {
            *(float4*)&C[(size_t)gr * NOUT + colBase + tx * TN + j] =
                make_float4(accf[i][j], accf[i][j+1], accf[i][j+2], accf[i][j+3]);
            if (HALF_OUT) {
                __half2* hp = (__half2*)&Ch[(size_t)gr * NOUT + colBase + tx * TN + j];
                hp[0] = __floats2half2_rn(accf[i][j],   accf[i][j+1]);
                hp[1] = __floats2half2_rn(accf[i][j+2], accf[i][j+3]);
            }
        }
    }
    // fused attention logits
    if (DO_ATT) {
        constexpr int GRP = 64 / TN;          // threads per head: 8 (BN=128) / 16 (BN=64)
        float svec[TN], dvec[TN];
#pragma unroll
        for (int j = 0; j < TN; j++) {
            svec[j] = att_s[colBase + tx * TN + j];
            dvec[j] = att_d[colBase + tx * TN + j];
        }
        int head = (colBase + tx * TN) / 64;
#pragma unroll
        for (int i = 0; i < 8; i++) {
            int gr = rowBase + ty * 8 + i;
            float ps = 0.f, pd = 0.f;
#pragma unroll
            for (int j = 0; j < TN; j++) {
                ps += accf[i][j] * svec[j];
                pd += accf[i][j] * dvec[j];
            }
#pragma unroll
            for (int o = 1; o < GRP; o <<= 1) {
                ps += __shfl_xor_sync(0xFFFFFFFFu, ps, o);
                pd += __shfl_xor_sync(0xFFFFFFFFu, pd, o);
            }
            if ((tx & (GRP - 1)) == 0 && gr < M) {
                atomicAdd(&AS[gr * HEADS + head], ps);
                atomicAdd(&AD[gr * HEADS + head], pd);
            }
        }
    }
}

// ---------------- per-node softmax (warp per node), writes alpha -------------
__global__ void softmax1_kernel() {
    int w = (blockIdx.x * blockDim.x + threadIdx.x) >> 5;
    int lane = threadIdx.x & 31;
    if (w >= N_NODES) return;
    int lo = g_rowptr[w], hi = g_rowptr[w + 1];
    float4 ad = *(const float4*)&g_ad1[w * 4];
    float m0 = -1e30f, m1 = -1e30f, m2 = -1e30f, m3 = -1e30f;
    float s0 = 0.f, s1 = 0.f, s2 = 0.f, s3 = 0.f;
    for (int k = lo + lane; k < hi; k += 32) {
        int s = g_csr_src[k];
        float4 as = *(const float4*)&g_as1[s * 4];
        float v0 = lrelu(as.x + ad.x), v1 = lrelu(as.y + ad.y);
        float v2 = lrelu(as.z + ad.z), v3 = lrelu(as.w + ad.w);
        if (v0 > m0) { s0 *= __expf(m0 - v0); m0 = v0; }  s0 += __expf(v0 - m0);
        if (v1 > m1) { s1 *= __expf(m1 - v1); m1 = v1; }  s1 += __expf(v1 - m1);
        if (v2 > m2) { s2 *= __expf(m2 - v2); m2 = v2; }  s2 += __expf(v2 - m2);
        if (v3 > m3) { s3 *= __expf(m3 - v3); m3 = v3; }  s3 += __expf(v3 - m3);
    }
#pragma unroll
    for (int off = 16; off; off >>= 1) {
        float mo, so, mn;
        mo = __shfl_xor_sync(0xFFFFFFFFu, m0, off); so = __shfl_xor_sync(0xFFFFFFFFu, s0, off);
        mn = fmaxf(m0, mo); s0 = s0 * __expf(m0 - mn) + so * __expf(mo - mn); m0 = mn;
        mo = __shfl_xor_sync(0xFFFFFFFFu, m1, off); so = __shfl_xor_sync(0xFFFFFFFFu, s1, off);
        mn = fmaxf(m1, mo); s1 = s1 * __expf(m1 - mn) + so * __expf(mo - mn); m1 = mn;
        mo = __shfl_xor_sync(0xFFFFFFFFu, m2, off); so = __shfl_xor_sync(0xFFFFFFFFu, s2, off);
        mn = fmaxf(m2, mo); s2 = s2 * __expf(m2 - mn) + so * __expf(mo - mn); m2 = mn;
        mo = __shfl_xor_sync(0xFFFFFFFFu, m3, off); so = __shfl_xor_sync(0xFFFFFFFFu, s3, off);
        mn = fmaxf(m3, mo); s3 = s3 * __expf(m3 - mn) + so * __expf(mo - mn); m3 = mn;
    }
    float i0 = 1.f / (s0 + EPS_DEN), i1 = 1.f / (s1 + EPS_DEN);
    float i2 = 1.f / (s2 + EPS_DEN), i3 = 1.f / (s3 + EPS_DEN);
    for (int k = lo + lane; k < hi; k += 32) {
        int s = g_csr_src[k];
        float4 as = *(const float4*)&g_as1[s * 4];
        float a0 = __expf(lrelu(as.x + ad.x) - m0) * i0;
        float a1 = __expf(lrelu(as.y + ad.y) - m1) * i1;
        float a2 = __expf(lrelu(as.z + ad.z) - m2) * i2;
        float a3 = __expf(lrelu(as.w + ad.w) - m3) * i3;
        *(float4*)&g_alpha1[k * 4] = make_float4(a0, a1, a2, a3);
    }
}

__global__ void softmax2_kernel() {
    int w = (blockIdx.x * blockDim.x + threadIdx.x) >> 5;
    int lane = threadIdx.x & 31;
    if (w >= N_NODES) return;
    int lo = g_rowptr[w], hi = g_rowptr[w + 1];
    float ad = g_ad2[w];
    float m = -1e30f, s = 0.f;
    for (int k = lo + lane; k < hi; k += 32) {
        float v = lrelu(g_as2[g_csr_src[k]] + ad);
        if (v > m) { s *= __expf(m - v); m = v; }
        s += __expf(v - m);
    }
#pragma unroll
    for (int off = 16; off; off >>= 1) {
        float mo = __shfl_xor_sync(0xFFFFFFFFu, m, off);
        float so = __shfl_xor_sync(0xFFFFFFFFu, s, off);
        float mn = fmaxf(m, mo);
        s = s * __expf(m - mn) + so * __expf(mo - mn);
        m = mn;
    }
    float inv = 1.f / (s + EPS_DEN);
    for (int k = lo + lane; k < hi; k += 32) {
        float v = lrelu(g_as2[g_csr_src[k]] + ad);
        g_alpha2[k] = __expf(v - m) * inv;
    }
}

// ---------------- aggregation (fp16 half2 gathers) ----------------------------
__global__ __launch_bounds__(128)
void agg1_kernel(const float* __restrict__ b1) {
    int n = blockIdx.x;
    int c2 = threadIdx.x;               // channels 2*c2, 2*c2+1
    int h = c2 >> 5;
    int lo = g_rowptr[n], hi = g_rowptr[n + 1];
    const __half2* H = (const __half2*)g_h1h;
    float ax = 0.f, ay = 0.f, bx = 0.f, by = 0.f;
    int k = lo;
    for (; k + 1 < hi; k += 2) {
        int s0 = g_csr_src[k], s1 = g_csr_src[k + 1];
        float a0 = g_alpha1[k * 4 + h], a1 = g_alpha1[(k + 1) * 4 + h];
        float2 v0 = __half22float2(__ldg(&H[(size_t)s0 * 128 + c2]));
        float2 v1 = __half22float2(__ldg(&H[(size_t)s1 * 128 + c2]));
        ax += a0 * v0.x; ay += a0 * v0.y;
        bx += a1 * v1.x; by += a1 * v1.y;
    }
    if (k < hi) {
        int s0 = g_csr_src[k];
        float a0 = g_alpha1[k * 4 + h];
        float2 v0 = __half22float2(__ldg(&H[(size_t)s0 * 128 + c2]));
        ax += a0 * v0.x; ay += a0 * v0.y;
    }
    float vx = ax + bx + b1[2 * c2];
    float vy = ay + by + b1[2 * c2 + 1];
    float2 r;
    r.x = vx > 0.f ? vx : expm1f(vx);
    r.y = vy > 0.f ? vy : expm1f(vy);
    *(float2*)&g_x2[(size_t)n * HC1 + 2 * c2] = r;
}

__global__ __launch_bounds__(32)
void agg2_kernel(float* __restrict__ out, const float* __restrict__ b2) {
    int n = blockIdx.x;
    int c2 = threadIdx.x;               // channels 2*c2, 2*c2+1
    int lo = g_rowptr[n], hi = g_rowptr[n + 1];
    const __half2* H = (const __half2*)g_h2h;
    float ax = 0.f, ay = 0.f, bx = 0.f, by = 0.f;
    int k = lo;
    for (; k + 1 < hi; k += 2) {
        int s0 = g_csr_src[k], s1 = g_csr_src[k + 1];
        float a0 = g_alpha2[k], a1 = g_alpha2[k + 1];
        float2 v0 = __half22float2(__ldg(&H[(size_t)s0 * 32 + c2]));
        float2 v1 = __half22float2(__ldg(&H[(size_t)s1 * 32 + c2]));
        ax += a0 * v0.x; ay += a0 * v0.y;
        bx += a1 * v1.x; by += a1 * v1.y;
    }
    if (k < hi) {
        int s0 = g_csr_src[k];
        float a0 = g_alpha2[k];
        float2 v0 = __half22float2(__ldg(&H[(size_t)s0 * 32 + c2]));
        ax += a0 * v0.x; ay += a0 * v0.y;
    }
    float2 r;
    r.x = ax + bx + b2[2 * c2];
    r.y = ay + by + b2[2 * c2 + 1];
    *(float2*)&out[(size_t)n * C2 + 2 * c2] = r;
}

// ---------------- launch ------------------------------------------------------
static inline int cdiv(long long a, int b) { return (int)((a + b - 1) / b); }

extern "C" void kernel_launch(void* const* d_in, const int* in_sizes, int n_in,
                              void* d_out, int out_size) {
    const float* x        = (const float*)d_in[0];
    const void*  ei       = d_in[1];
    const float* W1       = (const float*)d_in[2];
    const float* att_src1 = (const float*)d_in[3];
    const float* att_dst1 = (const float*)d_in[4];
    const float* b1       = (const float*)d_in[5];
    const float* W2       = (const float*)d_in[6];
    const float* att_src2 = (const float*)d_in[7];
    const float* att_dst2 = (const float*)d_in[8];
    const float* b2       = (const float*)d_in[9];
    float* out = (float*)d_out;

    float *h1, *x2, *h2, *as1, *ad1, *as2, *ad2;
    __half *h1h, *h2h;
    cudaGetSymbolAddress((void**)&h1, g_h1);
    cudaGetSymbolAddress((void**)&x2, g_x2);
    cudaGetSymbolAddress((void**)&h2, g_h2);
    cudaGetSymbolAddress((void**)&h1h, g_h1h);
    cudaGetSymbolAddress((void**)&h2h, g_h2h);
    cudaGetSymbolAddress((void**)&as1, g_as1);
    cudaGetSymbolAddress((void**)&ad1, g_ad1);
    cudaGetSymbolAddress((void**)&as2, g_as2);
    cudaGetSymbolAddress((void**)&ad2, g_ad2);

    const int T = 256;

    detzero_kernel<<<cdiv(N_NODES, T), T>>>((const int*)ei);
    edges_kernel<<<cdiv(ET, T), T>>>(ei);
    // #3: sgemm1 with fused att1 logits (in profiler capture window)
    {
        dim3 grid(HC1 / 128, cdiv(N_NODES, 128));
        sgemm_kernel<F_IN, HC1, 128, true, true><<<grid, T>>>(
            x, W1, h1, h1h, att_src1, att_dst1, as1, ad1, N_NODES);
    }
    scan_partial_kernel<<<NBLK, SCAN_B>>>();
    scan_tops_kernel<<<1, 32>>>();
    scan_final_kernel<<<NBLK, SCAN_B>>>();
    scatter_kernel<<<cdiv(ET, T), T>>>();
    softmax1_kernel<<<cdiv((long long)N_NODES * 32, T), T>>>();
    agg1_kernel<<<N_NODES, 128>>>(b1);
    // sgemm2 with fused att2 logits + fp16 mirror
    {
        dim3 grid(C2 / 64, cdiv(N_NODES, 128));
        sgemm_kernel<HC1, C2, 64, true, true><<<grid, T>>>(
            x2, W2, h2, h2h, att_src2, att_dst2, as2, ad2, N_NODES);
    }
    softmax2_kernel<<<cdiv((long long)N_NODES * 32, T), T>>>();
    agg2_kernel<<<N_NODES, 32>>>(out, b2);
}

// round 10
// speedup vs baseline: 1.8738x; 1.0067x over previous
#include <cuda_runtime.h>
#include <cuda_fp16.h>
#include <math.h>

#define N_NODES 50000
#define E_EDGES 800000
#define ET      (E_EDGES + N_NODES)   // 850000 edges incl. self loops
#define F_IN    128
#define H1      4
#define C1      64
#define HC1     256
#define C2      64
#define NEG_SLOPE 0.2f
#define EPS_DEN 1e-16f
#define SCAN_B  1024
#define NBLK    ((N_NODES + SCAN_B - 1) / SCAN_B)   // 49

// ---------------- scratch (device globals; 16B-aligned for float4) -----------
__device__ __align__(16) float  g_h1 [N_NODES * HC1];
__device__ __align__(16) __half g_h1h[N_NODES * HC1];
__device__ __align__(16) float  g_x2 [N_NODES * HC1];
__device__ __align__(16) float  g_h2 [N_NODES * C2];
__device__ __align__(16) __half g_h2h[N_NODES * C2];
__device__ __align__(16) float  g_as1[N_NODES * H1];
__device__ __align__(16) float  g_ad1[N_NODES * H1];
__device__ __align__(16) float  g_as2[N_NODES];
__device__ __align__(16) float  g_ad2[N_NODES];
__device__ __align__(16) float  g_alpha1[ET * H1];
__device__ __align__(16) float  g_alpha2[ET];
__device__ __align__(16) int    g_src[ET];
__device__ __align__(16) int    g_dst[ET];
__device__ __align__(16) int    g_csr_src[ET];
__device__ __align__(16) int    g_rowptr[N_NODES + 1];
__device__ __align__(16) int    g_cursor[N_NODES];
__device__ __align__(16) int    g_deg[N_NODES];
__device__ __align__(16) int    g_bsum[NBLK];
__device__ __align__(16) int    g_boff[NBLK];
__device__ int g_is64;

// ---------------- helpers ----------------------------------------------------
__device__ __forceinline__ int clampN(int v) {
    return v < 0 ? 0 : (v >= N_NODES ? N_NODES - 1 : v);
}
__device__ __forceinline__ float lrelu(float v) {
    return v > 0.f ? v : NEG_SLOPE * v;
}
__device__ __forceinline__ void fma2(unsigned long long& acc,
                                     unsigned long long a, unsigned long long b) {
    asm("fma.rn.f32x2 %0, %1, %2, %0;" : "+l"(acc) : "l"(a), "l"(b));
}
__device__ __forceinline__ unsigned long long pack2(float lo, float hi) {
    unsigned long long r;
    asm("mov.b64 %0, {%1, %2};" : "=l"(r) : "f"(lo), "f"(hi));
    return r;
}
__device__ __forceinline__ float2 unpack2(unsigned long long v) {
    float2 r;
    asm("mov.b64 {%0, %1}, %2;" : "=f"(r.x), "=f"(r.y) : "l"(v));
    return r;
}

// ---------------- detect dtype + zero accumulators ----------------------------
__global__ void detzero_kernel(const int* __restrict__ ei32) {
    int i = blockIdx.x * blockDim.x + threadIdx.x;
    if (i < N_NODES) {
        g_deg[i] = 0;
        g_as2[i] = 0.f;
        g_ad2[i] = 0.f;
#pragma unroll
        for (int h = 0; h < H1; h++) {
            g_as1[i * H1 + h] = 0.f;
            g_ad1[i * H1 + h] = 0.f;
        }
    }
    if (blockIdx.x == 0 && threadIdx.x < 32) {
        int lane = threadIdx.x;
        int v = ei32[2 * lane + 1] | ei32[2 * (lane + 32) + 1] |
                ei32[2 * (lane + 64) + 1] | ei32[2 * (lane + 96) + 1];
#pragma unroll
        for (int o = 16; o; o >>= 1) v |= __shfl_xor_sync(0xFFFFFFFFu, v, o);
        if (lane == 0) g_is64 = (v == 0) ? 1 : 0;
    }
}

__global__ void edges_kernel(const void* __restrict__ ei) {
    int i = blockIdx.x * blockDim.x + threadIdx.x;
    if (i >= ET) return;
    int s, d;
    if (i < E_EDGES) {
        if (g_is64) {
            const long long* p = (const long long*)ei;
            s = (int)p[i];  d = (int)p[E_EDGES + i];
        } else {
            const int* p = (const int*)ei;
            s = p[i];  d = p[E_EDGES + i];
        }
        s = clampN(s); d = clampN(d);
    } else {
        s = d = i - E_EDGES;
    }
    g_src[i] = s;
    g_dst[i] = d;
    atomicAdd(&g_deg[d], 1);
}

// ---------------- 3-phase parallel scan of g_deg -> g_rowptr ------------------
__global__ __launch_bounds__(SCAN_B) void scan_partial_kernel() {
    __shared__ int red[32];
    int i = blockIdx.x * SCAN_B + threadIdx.x;
    int v = (i < N_NODES) ? g_deg[i] : 0;
#pragma unroll
    for (int o = 16; o; o >>= 1) v += __shfl_down_sync(0xFFFFFFFFu, v, o);
    if ((threadIdx.x & 31) == 0) red[threadIdx.x >> 5] = v;
    __syncthreads();
    if (threadIdx.x < 32) {
        int r = red[threadIdx.x];
#pragma unroll
        for (int o = 16; o; o >>= 1) r += __shfl_down_sync(0xFFFFFFFFu, r, o);
        if (threadIdx.x == 0) g_bsum[blockIdx.x] = r;
    }
}

__global__ void scan_tops_kernel() {
    int lane = threadIdx.x;
    int v0 = (lane < NBLK) ? g_bsum[lane] : 0;
    int v1 = (lane + 32 < NBLK) ? g_bsum[lane + 32] : 0;
    int a = v0;
#pragma unroll
    for (int o = 1; o < 32; o <<= 1) {
        int t = __shfl_up_sync(0xFFFFFFFFu, a, o);
        if (lane >= o) a += t;
    }
    int tot0 = __shfl_sync(0xFFFFFFFFu, a, 31);
    int b = v1;
#pragma unroll
    for (int o = 1; o < 32; o <<= 1) {
        int t = __shfl_up_sync(0xFFFFFFFFu, b, o);
        if (lane >= o) b += t;
    }
    b += tot0;
    if (lane < NBLK) g_boff[lane] = a - v0;
    if (lane + 32 < NBLK) g_boff[lane + 32] = b - v1;
    if (lane == 31) g_rowptr[N_NODES] = (NBLK > 32) ? __shfl_sync(0xFFFFFFFFu, b, 31)
                                                    : tot0;
}

__global__ __launch_bounds__(SCAN_B) void scan_final_kernel() {
    __shared__ int warp_tot[32];
    int i = blockIdx.x * SCAN_B + threadIdx.x;
    int v = (i < N_NODES) ? g_deg[i] : 0;
    int lane = threadIdx.x & 31, w = threadIdx.x >> 5;
    int a = v;
#pragma unroll
    for (int o = 1; o < 32; o <<= 1) {
        int t = __shfl_up_sync(0xFFFFFFFFu, a, o);
        if (lane >= o) a += t;
    }
    if (lane == 31) warp_tot[w] = a;
    __syncthreads();
    if (threadIdx.x < 32) {
        int t = warp_tot[threadIdx.x];
        int s = t;
#pragma unroll
        for (int o = 1; o < 32; o <<= 1) {
            int u = __shfl_up_sync(0xFFFFFFFFu, s, o);
            if (threadIdx.x >= o) s += u;
        }
        warp_tot[threadIdx.x] = s - t;
    }
    __syncthreads();
    int excl = a - v + warp_tot[w] + g_boff[blockIdx.x];
    if (i < N_NODES) { g_rowptr[i] = excl; g_cursor[i] = excl; }
}

__global__ void scatter_kernel() {
    int i = blockIdx.x * blockDim.x + threadIdx.x;
    if (i >= ET) return;
    int pos = atomicAdd(&g_cursor[g_dst[i]], 1);
    g_csr_src[pos] = g_src[i];
}

// ---------------- SGEMM via packed f32x2 FMA, fused logits epilogue -----------
template<int K, int NOUT, int BN, bool HALF_OUT, bool DO_ATT>
__global__ __launch_bounds__(256)
void sgemm_kernel(const float* __restrict__ A, const float* __restrict__ B,
                  float* __restrict__ C, __half* __restrict__ Ch,
                  const float* __restrict__ att_s, const float* __restrict__ att_d,
                  float* __restrict__ AS, float* __restrict__ AD, int M) {
    constexpr int TN  = BN / 16;
    constexpr int TN2 = TN / 2;
    constexpr int HEADS = NOUT / 64;
    __shared__ float As[16][128];
    __shared__ float Bs[16][BN];
    int t = threadIdx.x;
    int tx = t & 15, ty = t >> 4;
    int rowBase = blockIdx.y * 128;
    int colBase = blockIdx.x * BN;
    unsigned long long acc[8][TN2];
#pragma unroll
    for (int i = 0; i < 8; i++)
#pragma unroll
        for (int j = 0; j < TN2; j++) acc[i][j] = 0ull;

    for (int kt = 0; kt < K; kt += 16) {
#pragma unroll
        for (int i = 0; i < 2; i++) {
            int c = t * 2 + i;
            int ar = c >> 2, k4 = c & 3;
            int gr = rowBase + ar;
            float4 av = make_float4(0.f, 0.f, 0.f, 0.f);
            if (gr < M) av = *(const float4*)&A[(size_t)gr * K + kt + k4 * 4];
            As[k4 * 4 + 0][ar] = av.x;
            As[k4 * 4 + 1][ar] = av.y;
            As[k4 * 4 + 2][ar] = av.z;
            As[k4 * 4 + 3][ar] = av.w;
        }
        if (BN == 128) {
#pragma unroll
            for (int i = 0; i < 2; i++) {
                int c = t * 2 + i;
                int bk = c >> 5, c4 = c & 31;
                *(float4*)&Bs[bk][c4 * 4] =
                    *(const float4*)&B[(size_t)(kt + bk) * NOUT + colBase + c4 * 4];
            }
        } else {
            int bk = t >> 4, c4 = t & 15;
            *(float4*)&Bs[bk][c4 * 4] =
                *(const float4*)&B[(size_t)(kt + bk) * NOUT + colBase + c4 * 4];
        }
        __syncthreads();
#pragma unroll
        for (int k = 0; k < 16; k++) {
            float4 a0 = *(const float4*)&As[k][ty * 8];
            float4 a1 = *(const float4*)&As[k][ty * 8 + 4];
            unsigned long long ap[8];
            ap[0] = pack2(a0.x, a0.x); ap[1] = pack2(a0.y, a0.y);
            ap[2] = pack2(a0.z, a0.z); ap[3] = pack2(a0.w, a0.w);
            ap[4] = pack2(a1.x, a1.x); ap[5] = pack2(a1.y, a1.y);
            ap[6] = pack2(a1.z, a1.z); ap[7] = pack2(a1.w, a1.w);
            unsigned long long bp[TN2];
            {
                float4 b0 = *(const float4*)&Bs[k][tx * TN];
                bp[0] = pack2(b0.x, b0.y);
                bp[1] = pack2(b0.z, b0.w);
                if (TN2 == 4) {
                    float4 b1 = *(const float4*)&Bs[k][tx * TN + 4];
                    bp[2] = pack2(b1.x, b1.y);
                    bp[3] = pack2(b1.z, b1.w);
                }
            }
#pragma unroll
            for (int i = 0; i < 8; i++)
#pragma unroll
                for (int j = 0; j < TN2; j++)
                    fma2(acc[i][j], ap[i], bp[j]);
        }
        __syncthreads();
    }
    float accf[8][TN];
#pragma unroll
    for (int i = 0; i < 8; i++)
#pragma unroll
        for (int j = 0; j < TN2; j++) {
            float2 v = unpack2(acc[i][j]);
            accf[i][2 * j] = v.x;
            accf[i][2 * j + 1] = v.y;
        }
#pragma unroll
    for (int i = 0; i < 8; i++) {
        int gr = rowBase + ty * 8 + i;
        if (gr >= M) break;
#pragma unroll
        for (int j = 0; j < TN; j += 4) {
            *(float4*)&C[(size_t)gr * NOUT + colBase + tx * TN + j] =
                make_float4(accf[i][j], accf[i][j+1], accf[i][j+2], accf[i][j+3]);
            if (HALF_OUT) {
                __half2* hp = (__half2*)&Ch[(size_t)gr * NOUT + colBase + tx * TN + j];
                hp[0] = __floats2half2_rn(accf[i][j],   accf[i][j+1]);
                hp[1] = __floats2half2_rn(accf[i][j+2], accf[i][j+3]);
            }
        }
    }
    if (DO_ATT) {
        constexpr int GRP = 64 / TN;
        float svec[TN], dvec[TN];
#pragma unroll
        for (int j = 0; j < TN; j++) {
            svec[j] = att_s[colBase + tx * TN + j];
            dvec[j] = att_d[colBase + tx * TN + j];
        }
        int head = (colBase + tx * TN) / 64;
#pragma unroll
        for (int i = 0; i < 8; i++) {
            int gr = rowBase + ty * 8 + i;
            float ps = 0.f, pd = 0.f;
#pragma unroll
            for (int j = 0; j < TN; j++) {
                ps += accf[i][j] * svec[j];
                pd += accf[i][j] * dvec[j];
            }
#pragma unroll
            for (int o = 1; o < GRP; o <<= 1) {
                ps += __shfl_xor_sync(0xFFFFFFFFu, ps, o);
                pd += __shfl_xor_sync(0xFFFFFFFFu, pd, o);
            }
            if ((tx & (GRP - 1)) == 0 && gr < M) {
                atomicAdd(&AS[gr * HEADS + head], ps);
                atomicAdd(&AD[gr * HEADS + head], pd);
            }
        }
    }
}

// ---------------- per-node softmax (warp per node), writes alpha -------------
__global__ void softmax1_kernel() {
    int w = (blockIdx.x * blockDim.x + threadIdx.x) >> 5;
    int lane = threadIdx.x & 31;
    if (w >= N_NODES) return;
    int lo = g_rowptr[w], hi = g_rowptr[w + 1];
    float4 ad = *(const float4*)&g_ad1[w * 4];
    float m0 = -1e30f, m1 = -1e30f, m2 = -1e30f, m3 = -1e30f;
    float s0 = 0.f, s1 = 0.f, s2 = 0.f, s3 = 0.f;
    for (int k = lo + lane; k < hi; k += 32) {
        int s = g_csr_src[k];
        float4 as = *(const float4*)&g_as1[s * 4];
        float v0 = lrelu(as.x + ad.x), v1 = lrelu(as.y + ad.y);
        float v2 = lrelu(as.z + ad.z), v3 = lrelu(as.w + ad.w);
        if (v0 > m0) { s0 *= __expf(m0 - v0); m0 = v0; }  s0 += __expf(v0 - m0);
        if (v1 > m1) { s1 *= __expf(m1 - v1); m1 = v1; }  s1 += __expf(v1 - m1);
        if (v2 > m2) { s2 *= __expf(m2 - v2); m2 = v2; }  s2 += __expf(v2 - m2);
        if (v3 > m3) { s3 *= __expf(m3 - v3); m3 = v3; }  s3 += __expf(v3 - m3);
    }
#pragma unroll
    for (int off = 16; off; off >>= 1) {
        float mo, so, mn;
        mo = __shfl_xor_sync(0xFFFFFFFFu, m0, off); so = __shfl_xor_sync(0xFFFFFFFFu, s0, off);
        mn = fmaxf(m0, mo); s0 = s0 * __expf(m0 - mn) + so * __expf(mo - mn); m0 = mn;
        mo = __shfl_xor_sync(0xFFFFFFFFu, m1, off); so = __shfl_xor_sync(0xFFFFFFFFu, s1, off);
        mn = fmaxf(m1, mo); s1 = s1 * __expf(m1 - mn) + so * __expf(mo - mn); m1 = mn;
        mo = __shfl_xor_sync(0xFFFFFFFFu, m2, off); so = __shfl_xor_sync(0xFFFFFFFFu, s2, off);
        mn = fmaxf(m2, mo); s2 = s2 * __expf(m2 - mn) + so * __expf(mo - mn); m2 = mn;
        mo = __shfl_xor_sync(0xFFFFFFFFu, m3, off); so = __shfl_xor_sync(0xFFFFFFFFu, s3, off);
        mn = fmaxf(m3, mo); s3 = s3 * __expf(m3 - mn) + so * __expf(mo - mn); m3 = mn;
    }
    float i0 = 1.f / (s0 + EPS_DEN), i1 = 1.f / (s1 + EPS_DEN);
    float i2 = 1.f / (s2 + EPS_DEN), i3 = 1.f / (s3 + EPS_DEN);
    for (int k = lo + lane; k < hi; k += 32) {
        int s = g_csr_src[k];
        float4 as = *(const float4*)&g_as1[s * 4];
        float a0 = __expf(lrelu(as.x + ad.x) - m0) * i0;
        float a1 = __expf(lrelu(as.y + ad.y) - m1) * i1;
        float a2 = __expf(lrelu(as.z + ad.z) - m2) * i2;
        float a3 = __expf(lrelu(as.w + ad.w) - m3) * i3;
        *(float4*)&g_alpha1[k * 4] = make_float4(a0, a1, a2, a3);
    }
}

__global__ void softmax2_kernel() {
    int w = (blockIdx.x * blockDim.x + threadIdx.x) >> 5;
    int lane = threadIdx.x & 31;
    if (w >= N_NODES) return;
    int lo = g_rowptr[w], hi = g_rowptr[w + 1];
    float ad = g_ad2[w];
    float m = -1e30f, s = 0.f;
    for (int k = lo + lane; k < hi; k += 32) {
        float v = lrelu(g_as2[g_csr_src[k]] + ad);
        if (v > m) { s *= __expf(m - v); m = v; }
        s += __expf(v - m);
    }
#pragma unroll
    for (int off = 16; off; off >>= 1) {
        float mo = __shfl_xor_sync(0xFFFFFFFFu, m, off);
        float so = __shfl_xor_sync(0xFFFFFFFFu, s, off);
        float mn = fmaxf(m, mo);
        s = s * __expf(m - mn) + so * __expf(mo - mn);
        m = mn;
    }
    float inv = 1.f / (s + EPS_DEN);
    for (int k = lo + lane; k < hi; k += 32) {
        float v = lrelu(g_as2[g_csr_src[k]] + ad);
        g_alpha2[k] = __expf(v - m) * inv;
    }
}

// ---------------- aggregation (fp16 half2 gathers, 4-way unroll) --------------
__global__ __launch_bounds__(128)
void agg1_kernel(const float* __restrict__ b1) {
    int n = blockIdx.x;
    int c2 = threadIdx.x;               // channels 2*c2, 2*c2+1
    int h = c2 >> 5;
    int lo = g_rowptr[n], hi = g_rowptr[n + 1];
    const __half2* H = (const __half2*)g_h1h;
    float ax = 0.f, ay = 0.f, bx = 0.f, by = 0.f;
    float cx = 0.f, cy = 0.f, dx = 0.f, dy = 0.f;
    int k = lo;
    for (; k + 3 < hi; k += 4) {
        int s0 = g_csr_src[k],     s1 = g_csr_src[k + 1];
        int s2 = g_csr_src[k + 2], s3 = g_csr_src[k + 3];
        float a0 = g_alpha1[k * 4 + h],       a1 = g_alpha1[(k + 1) * 4 + h];
        float a2 = g_alpha1[(k + 2) * 4 + h], a3 = g_alpha1[(k + 3) * 4 + h];
        float2 v0 = __half22float2(__ldg(&H[(size_t)s0 * 128 + c2]));
        float2 v1 = __half22float2(__ldg(&H[(size_t)s1 * 128 + c2]));
        float2 v2 = __half22float2(__ldg(&H[(size_t)s2 * 128 + c2]));
        float2 v3 = __half22float2(__ldg(&H[(size_t)s3 * 128 + c2]));
        ax += a0 * v0.x; ay += a0 * v0.y;
        bx += a1 * v1.x; by += a1 * v1.y;
        cx += a2 * v2.x; cy += a2 * v2.y;
        dx += a3 * v3.x; dy += a3 * v3.y;
    }
    for (; k < hi; k++) {
        int s0 = g_csr_src[k];
        float a0 = g_alpha1[k * 4 + h];
        float2 v0 = __half22float2(__ldg(&H[(size_t)s0 * 128 + c2]));
        ax += a0 * v0.x; ay += a0 * v0.y;
    }
    float vx = (ax + bx) + (cx + dx) + b1[2 * c2];
    float vy = (ay + by) + (cy + dy) + b1[2 * c2 + 1];
    float2 r;
    r.x = vx > 0.f ? vx : expm1f(vx);
    r.y = vy > 0.f ? vy : expm1f(vy);
    *(float2*)&g_x2[(size_t)n * HC1 + 2 * c2] = r;
}

// 2 nodes per 64-thread block (warp per node), 4-way edge unroll
__global__ __launch_bounds__(64)
void agg2_kernel(float* __restrict__ out, const float* __restrict__ b2) {
    int n = blockIdx.x * 2 + (threadIdx.x >> 5);
    if (n >= N_NODES) return;
    int c2 = threadIdx.x & 31;          // channels 2*c2, 2*c2+1
    int lo = g_rowptr[n], hi = g_rowptr[n + 1];
    const __half2* H = (const __half2*)g_h2h;
    float ax = 0.f, ay = 0.f, bx = 0.f, by = 0.f;
    float cx = 0.f, cy = 0.f, dx = 0.f, dy = 0.f;
    int k = lo;
    for (; k + 3 < hi; k += 4) {
        int s0 = g_csr_src[k],     s1 = g_csr_src[k + 1];
        int s2 = g_csr_src[k + 2], s3 = g_csr_src[k + 3];
        float a0 = g_alpha2[k],     a1 = g_alpha2[k + 1];
        float a2 = g_alpha2[k + 2], a3 = g_alpha2[k + 3];
        float2 v0 = __half22float2(__ldg(&H[(size_t)s0 * 32 + c2]));
        float2 v1 = __half22float2(__ldg(&H[(size_t)s1 * 32 + c2]));
        float2 v2 = __half22float2(__ldg(&H[(size_t)s2 * 32 + c2]));
        float2 v3 = __half22float2(__ldg(&H[(size_t)s3 * 32 + c2]));
        ax += a0 * v0.x; ay += a0 * v0.y;
        bx += a1 * v1.x; by += a1 * v1.y;
        cx += a2 * v2.x; cy += a2 * v2.y;
        dx += a3 * v3.x; dy += a3 * v3.y;
    }
    for (; k < hi; k++) {
        int s0 = g_csr_src[k];
        float a0 = g_alpha2[k];
        float2 v0 = __half22float2(__ldg(&H[(size_t)s0 * 32 + c2]));
        ax += a0 * v0.x; ay += a0 * v0.y;
    }
    float2 r;
    r.x = (ax + bx) + (cx + dx) + b2[2 * c2];
    r.y = (ay + by) + (cy + dy) + b2[2 * c2 + 1];
    *(float2*)&out[(size_t)n * C2 + 2 * c2] = r;
}

// ---------------- launch ------------------------------------------------------
static inline int cdiv(long long a, int b) { return (int)((a + b - 1) / b); }

extern "C" void kernel_launch(void* const* d_in, const int* in_sizes, int n_in,
                              void* d_out, int out_size) {
    const float* x        = (const float*)d_in[0];
    const void*  ei       = d_in[1];
    const float* W1       = (const float*)d_in[2];
    const float* att_src1 = (const float*)d_in[3];
    const float* att_dst1 = (const float*)d_in[4];
    const float* b1       = (const float*)d_in[5];
    const float* W2       = (const float*)d_in[6];
    const float* att_src2 = (const float*)d_in[7];
    const float* att_dst2 = (const float*)d_in[8];
    const float* b2       = (const float*)d_in[9];
    float* out = (float*)d_out;

    float *h1, *x2, *h2, *as1, *ad1, *as2, *ad2;
    __half *h1h, *h2h;
    cudaGetSymbolAddress((void**)&h1, g_h1);
    cudaGetSymbolAddress((void**)&x2, g_x2);
    cudaGetSymbolAddress((void**)&h2, g_h2);
    cudaGetSymbolAddress((void**)&h1h, g_h1h);
    cudaGetSymbolAddress((void**)&h2h, g_h2h);
    cudaGetSymbolAddress((void**)&as1, g_as1);
    cudaGetSymbolAddress((void**)&ad1, g_ad1);
    cudaGetSymbolAddress((void**)&as2, g_as2);
    cudaGetSymbolAddress((void**)&ad2, g_ad2);

    const int T = 256;

    detzero_kernel<<<cdiv(N_NODES, T), T>>>((const int*)ei);        // #1
    edges_kernel<<<cdiv(ET, T), T>>>(ei);                           // #2
    scan_partial_kernel<<<NBLK, SCAN_B>>>();                        // #3
    // #4: sgemm1 — in the profiler's capture slot this round
    {
        dim3 grid(HC1 / 128, cdiv(N_NODES, 128));
        sgemm_kernel<F_IN, HC1, 128, true, true><<<grid, T>>>(
            x, W1, h1, h1h, att_src1, att_dst1, as1, ad1, N_NODES);
    }
    scan_tops_kernel<<<1, 32>>>();
    scan_final_kernel<<<NBLK, SCAN_B>>>();
    scatter_kernel<<<cdiv(ET, T), T>>>();
    softmax1_kernel<<<cdiv((long long)N_NODES * 32, T), T>>>();
    agg1_kernel<<<N_NODES, 128>>>(b1);
    {
        dim3 grid(C2 / 64, cdiv(N_NODES, 128));
        sgemm_kernel<HC1, C2, 64, true, true><<<grid, T>>>(
            x2, W2, h2, h2h, att_src2, att_dst2, as2, ad2, N_NODES);
    }
    softmax2_kernel<<<cdiv((long long)N_NODES * 32, T), T>>>();
    agg2_kernel<<<cdiv(N_NODES, 2), 64>>>(out, b2);
}